// round 13
// baseline (speedup 1.0000x reference)
#include <cuda_runtime.h>
#include <cuda_bf16.h>
#include <math.h>

#define B_   32
#define HW_  4096
#define C1O  64
#define C2O  128

// ---------------- scratch ----------------------------------------------------
__device__ float g_h1c[(size_t)B_ * HW_ * C1O];        // channel-last h1
__device__ float g_partial[(size_t)4096 * C2O];        // pooled partials (blk*2+nw)
__device__ float g_pool_seg[256 * C2O];                // stage-1 reduced partials
#define WF1_N (2 * 8 * 36 * 128)
#define WF2_N (2 * 2 * 36 * 128)
__device__ unsigned g_wfrag[WF1_N];                    // conv2 A-frags [term][mt][K][lane*4+r]
__device__ unsigned g_wfrag2[WF2_N];                   // off2 A-frags  [term][mt][K][lane*4+r]

typedef unsigned long long ull;

// ---------------- f32x2 helpers ----------------------------------------------
__device__ __forceinline__ ull fma2(ull a, ull b, ull c) {
    ull d; asm("fma.rn.f32x2 %0, %1, %2, %3;" : "=l"(d) : "l"(a), "l"(b), "l"(c)); return d;
}
__device__ __forceinline__ ull dup2(float v) {
    ull d; unsigned r = __float_as_uint(v);
    asm("mov.b64 %0, {%1, %1};" : "=l"(d) : "r"(r)); return d;
}
__device__ __forceinline__ float2 unpack2(ull v) {
    unsigned lo, hi; asm("mov.b64 {%0, %1}, %2;" : "=r"(lo), "=r"(hi) : "l"(v));
    return make_float2(__uint_as_float(lo), __uint_as_float(hi));
}

// ---------------- mma helpers ------------------------------------------------
__device__ __forceinline__ unsigned smem_u32(const void* p) {
    unsigned a;
    asm("{ .reg .u64 t; cvta.to.shared.u64 t, %1; cvt.u32.u64 %0, t; }" : "=r"(a) : "l"(p));
    return a;
}
__device__ __forceinline__ unsigned pack_bf16(float v0, float v1) {  // low=v0, high=v1
    unsigned d; asm("cvt.rn.bf16x2.f32 %0, %1, %2;" : "=r"(d) : "f"(v1), "f"(v0)); return d;
}
__device__ __forceinline__ void ldsm4(unsigned& r0, unsigned& r1, unsigned& r2, unsigned& r3,
                                      unsigned addr) {
    asm volatile("ldmatrix.sync.aligned.m8n8.x4.shared.b16 {%0,%1,%2,%3}, [%4];"
                 : "=r"(r0), "=r"(r1), "=r"(r2), "=r"(r3) : "r"(addr));
}
__device__ __forceinline__ void mma_bf16(float* c, const uint4& a, unsigned b0, unsigned b1) {
    asm volatile(
        "mma.sync.aligned.m16n8k16.row.col.f32.bf16.bf16.f32 "
        "{%0,%1,%2,%3}, {%4,%5,%6,%7}, {%8,%9}, {%0,%1,%2,%3};"
        : "+f"(c[0]), "+f"(c[1]), "+f"(c[2]), "+f"(c[3])
        : "r"(a.x), "r"(a.y), "r"(a.z), "r"(a.w), "r"(b0), "r"(b1));
}

// ---------------- K0: build A-fragment weight images -------------------------
__global__ void k0_prep(const float* __restrict__ cw, const float* __restrict__ w2)
{
    int idx = blockIdx.x * 256 + threadIdx.x;
    if (idx < WF1_N) {
        int r = idx & 3, lane = (idx >> 2) & 31;
        int K = (idx >> 7) % 36;
        int mt = (idx / (128 * 36)) & 7;
        int wt = idx / (128 * 36 * 8);
        int g = lane >> 2, t = lane & 3;
        int co = mt * 16 + g + ((r & 1) ? 8 : 0);
        int kl = 2 * t + ((r & 2) ? 8 : 0);
        float w[2];
        #pragma unroll
        for (int j = 0; j < 2; j++) {
            int e = K * 16 + kl + j;
            int s = e / 192, es = e % 192;
            int tapl = es >> 6, ci = es & 63;
            float wv = cw[co * 576 + ci * 9 + s * 3 + tapl];
            if (wt == 0) w[j] = wv;
            else {
                float hi = __bfloat162float(__float2bfloat16(wv));
                w[j] = wv - hi;
            }
        }
        g_wfrag[idx] = pack_bf16(w[0], w[1]);
    } else if (idx < WF1_N + WF2_N) {
        int i2 = idx - WF1_N;
        int r = i2 & 3, lane = (i2 >> 2) & 31;
        int K = (i2 >> 7) % 36;
        int mt = (i2 / (128 * 36)) & 1;
        int wt = i2 / (128 * 36 * 2);
        int g = lane >> 2, t = lane & 3;
        int co = mt * 16 + g + ((r & 1) ? 8 : 0);
        int kl = 2 * t + ((r & 2) ? 8 : 0);
        float w[2];
        #pragma unroll
        for (int j = 0; j < 2; j++) {
            int e = K * 16 + kl + j;
            int s = e / 192, es = e % 192;
            int tapl = es >> 6, ci = es & 63;
            float wv = (co < 18) ? w2[co * 576 + ci * 9 + s * 3 + tapl] : 0.f;
            if (wt == 0) w[j] = wv;
            else {
                float hi = __bfloat162float(__float2bfloat16(wv));
                w[j] = wv - hi;
            }
        }
        g_wfrag2[i2] = pack_bf16(w[0], w[1]);
    }
}

// ---------------- K1: offset1 + deform conv1 + bn1 + relu (f32x2) ------------
__global__ void __launch_bounds__(128)
k1_layer1(const float* __restrict__ x,
          const float* __restrict__ ow, const float* __restrict__ ob,
          const float* __restrict__ cw, const float* __restrict__ cb,
          const float* __restrict__ g1, const float* __restrict__ be1,
          const float* __restrict__ m1, const float* __restrict__ v1)
{
    __shared__ float s_owT[27 * 20];   // [j][o] pad 20
    __shared__ float s_cwT[27 * 64];   // [j][co]
    __shared__ float s_ob[18];
    __shared__ float s_scale[64], s_bias[64];
    __shared__ float s_out[128 * 65];

    int tid = threadIdx.x;
    for (int i = tid; i < 486; i += 128) {
        int o = i / 27, j = i % 27;
        s_owT[j * 20 + o] = ow[i];
    }
    for (int i = tid; i < 54; i += 128) {          // pad o=18,19
        int j = i % 27, o = 18 + i / 27;
        s_owT[j * 20 + o] = 0.f;
    }
    for (int i = tid; i < 1728; i += 128) {
        int co = i / 27, j = i % 27;
        s_cwT[j * 64 + co] = cw[i];
    }
    if (tid < 18) s_ob[tid] = ob[tid];
    if (tid < 64) {
        float sc = g1[tid] * rsqrtf(v1[tid] + 1e-5f);
        s_scale[tid] = sc;
        s_bias[tid]  = be1[tid] + (cb[tid] - m1[tid]) * sc;
    }
    __syncthreads();

    int lin = blockIdx.x * 128 + tid;
    int b = lin >> 12, hw = lin & 4095, h = hw >> 6, w = hw & 63;
    const float* xb = x + (size_t)b * 3 * 4096;

    float xwin[27];
    #pragma unroll
    for (int ci = 0; ci < 3; ci++)
        #pragma unroll
        for (int kh = 0; kh < 3; kh++)
            #pragma unroll
            for (int kw = 0; kw < 3; kw++) {
                int yy = h + kh - 1, xx = w + kw - 1;
                float val = 0.f;
                if (yy >= 0 && yy < 64 && xx >= 0 && xx < 64)
                    val = xb[ci * 4096 + yy * 64 + xx];
                xwin[ci * 9 + kh * 3 + kw] = val;
            }

    // offsets: 18 outputs as 9(+1 pad) f32x2 pairs
    ull oacc[10];
    #pragma unroll
    for (int p = 0; p < 10; p++) oacc[p] = 0ull;
    #pragma unroll
    for (int j = 0; j < 27; j++) {
        ull vd = dup2(xwin[j]);
        const ulonglong2* wp = (const ulonglong2*)&s_owT[j * 20];
        #pragma unroll
        for (int p = 0; p < 5; p++) {
            ulonglong2 wq = wp[p];
            oacc[p * 2]     = fma2(wq.x, vd, oacc[p * 2]);
            oacc[p * 2 + 1] = fma2(wq.y, vd, oacc[p * 2 + 1]);
        }
    }
    float off[18];
    #pragma unroll
    for (int p = 0; p < 9; p++) {
        float2 f = unpack2(oacc[p]);
        off[2 * p]     = f.x + s_ob[2 * p];
        off[2 * p + 1] = f.y + s_ob[2 * p + 1];
    }

    float v[27];
    #pragma unroll
    for (int tap = 0; tap < 9; tap++) {
        float py = (float)(h + tap / 3 - 1) + off[tap * 2];
        float px = (float)(w + tap % 3 - 1) + off[tap * 2 + 1];
        float y0f = floorf(py), x0f = floorf(px);
        int y0 = (int)y0f, x0 = (int)x0f;
        float wy = py - y0f, wx = px - x0f;
        float w00 = (1.f - wy) * (1.f - wx), w01 = (1.f - wy) * wx;
        float w10 = wy * (1.f - wx),         w11 = wy * wx;
        bool vy0 = ((unsigned)y0 < 64u), vy1 = ((unsigned)(y0 + 1) < 64u);
        bool vx0 = ((unsigned)x0 < 64u), vx1 = ((unsigned)(x0 + 1) < 64u);
        long long i00 = (long long)y0 * 64 + x0;
        #pragma unroll
        for (int ci = 0; ci < 3; ci++) {
            const float* p = xb + ci * 4096;
            float c00 = (vy0 && vx0) ? p[i00]      : 0.f;
            float c01 = (vy0 && vx1) ? p[i00 + 1]  : 0.f;
            float c10 = (vy1 && vx0) ? p[i00 + 64] : 0.f;
            float c11 = (vy1 && vx1) ? p[i00 + 65] : 0.f;
            v[ci * 9 + tap] = c00 * w00 + c01 * w01 + c10 * w10 + c11 * w11;
        }
    }

    // conv outputs: 64 co in two halves of 32 (16 f32x2 pairs each)
    #pragma unroll
    for (int h2 = 0; h2 < 2; h2++) {
        ull acc2[16];
        #pragma unroll
        for (int p = 0; p < 16; p++) acc2[p] = 0ull;
        #pragma unroll
        for (int j = 0; j < 27; j++) {
            ull vd = dup2(v[j]);
            const ulonglong2* wp = (const ulonglong2*)&s_cwT[j * 64 + h2 * 32];
            #pragma unroll
            for (int p = 0; p < 8; p++) {
                ulonglong2 wq = wp[p];
                acc2[p * 2]     = fma2(wq.x, vd, acc2[p * 2]);
                acc2[p * 2 + 1] = fma2(wq.y, vd, acc2[p * 2 + 1]);
            }
        }
        #pragma unroll
        for (int p = 0; p < 16; p++) {
            int co = h2 * 32 + 2 * p;
            float2 f = unpack2(acc2[p]);
            s_out[tid * 65 + co]     = fmaxf(f.x * s_scale[co] + s_bias[co], 0.f);
            s_out[tid * 65 + co + 1] = fmaxf(f.y * s_scale[co + 1] + s_bias[co + 1], 0.f);
        }
    }
    __syncthreads();

    size_t base = (size_t)blockIdx.x * 128 * 64;
    for (int i = tid; i < 8192; i += 128)
        g_h1c[base + i] = s_out[(i >> 6) * 65 + (i & 63)];
}

// ---------------- K3 (fused): offset2 conv + deform conv2 + bn2 + relu + pool
#define VT_PITCH_B 400
#define VT_HI_OFF  0
#define VT_LO_OFF  25600
#define CWYX_OFF   51200
#define CYX_OFF    55808
#define SCALE_OFF  58112
#define BIAS_OFF   58624
#define SOFF_OFF   59136          // float[18*64]
#define K3_SMEM    63744

__global__ void __launch_bounds__(256, 3)
k3_fused(const float* __restrict__ b2, const float* __restrict__ cb,
         const float* __restrict__ g2, const float* __restrict__ be2,
         const float* __restrict__ m2, const float* __restrict__ v2)
{
    extern __shared__ char sm[];
    float2* s_wyx  = (float2*)(sm + CWYX_OFF);
    int*    s_yx   = (int*)(sm + CYX_OFF);
    float*  s_scale = (float*)(sm + SCALE_OFF);
    float*  s_bias  = (float*)(sm + BIAS_OFF);
    float*  s_off   = (float*)(sm + SOFF_OFF);
    unsigned smb = smem_u32(sm);

    int tid = threadIdx.x;
    int blk = blockIdx.x;
    int h = blk & 63, b = blk >> 6;

    if (tid < 128) {
        float sc = g2[tid] * rsqrtf(v2[tid] + 1e-5f);
        s_scale[tid] = sc;
        s_bias[tid]  = be2[tid] + (cb[tid] - m2[tid]) * sc;
    }

    const float* hb = g_h1c + (size_t)b * HW_ * C1O;
    int lane = tid & 31, wid = tid >> 5;
    int g = lane >> 2, t4 = lane & 3;
    int mlm = lane >> 3, rl = lane & 7;

    // ===================== Part 1: offsets (k2) ==============================
    {
        int mt = wid & 1, ng = wid >> 1;
        unsigned vb = smb + (unsigned)((ng * 16 + (mlm >> 1) * 8 + rl) * VT_PITCH_B + (mlm & 1) * 16);

        float acc[2][4];
        #pragma unroll
        for (int n = 0; n < 2; n++)
            #pragma unroll
            for (int r = 0; r < 4; r++) acc[n][r] = 0.f;

        const uint4* wf2 = (const uint4*)g_wfrag2;

        for (int s = 0; s < 3; s++) {
            int y = h + s - 1;
            bool rowv = ((unsigned)y < 64u);

            for (int u = tid; u < 1536; u += 256) {
                int c8 = u & 7, task = u >> 3;
                int tapl = task >> 6, loc = task & 63;
                int x = loc + tapl - 1;
                bool valid = rowv && ((unsigned)x < 64u);
                int ci0 = c8 * 8;
                const float4* p = (const float4*)(hb + ((long long)y * 64 + x) * 64 + ci0);
                float4 z = make_float4(0.f, 0.f, 0.f, 0.f);
                float4 va = valid ? p[0] : z;
                float4 vc = valid ? p[1] : z;

                uint4 hi4;
                hi4.x = pack_bf16(va.x, va.y); hi4.y = pack_bf16(va.z, va.w);
                hi4.z = pack_bf16(vc.x, vc.y); hi4.w = pack_bf16(vc.z, vc.w);
                float r0 = va.x - __uint_as_float(hi4.x << 16);
                float r1 = va.y - __uint_as_float(hi4.x & 0xffff0000u);
                float r2 = va.z - __uint_as_float(hi4.y << 16);
                float r3 = va.w - __uint_as_float(hi4.y & 0xffff0000u);
                float r4 = vc.x - __uint_as_float(hi4.z << 16);
                float r5 = vc.y - __uint_as_float(hi4.z & 0xffff0000u);
                float r6 = vc.z - __uint_as_float(hi4.w << 16);
                float r7 = vc.w - __uint_as_float(hi4.w & 0xffff0000u);
                uint4 lo4;
                lo4.x = pack_bf16(r0, r1); lo4.y = pack_bf16(r2, r3);
                lo4.z = pack_bf16(r4, r5); lo4.w = pack_bf16(r6, r7);

                unsigned off = (unsigned)(loc * VT_PITCH_B + (tapl * 64 + ci0) * 2);
                *(uint4*)(sm + VT_HI_OFF + off) = hi4;
                *(uint4*)(sm + VT_LO_OFF + off) = lo4;
            }
            __syncthreads();

            int ahb = (mt * 36 + s * 12) * 32 + lane;
            int alb = ahb + 2 * 36 * 32;
            #pragma unroll 1
            for (int k12 = 0; k12 < 12; k12++) {
                uint4 ah = wf2[ahb + k12 * 32];
                unsigned bh[4], bl[4];
                ldsm4(bh[0], bh[1], bh[2], bh[3], vb + VT_HI_OFF + (unsigned)(k12 * 32));
                ldsm4(bl[0], bl[1], bl[2], bl[3], vb + VT_LO_OFF + (unsigned)(k12 * 32));
                mma_bf16(acc[0], ah, bh[0], bh[1]);
                mma_bf16(acc[1], ah, bh[2], bh[3]);
                mma_bf16(acc[0], ah, bl[0], bl[1]);
                mma_bf16(acc[1], ah, bl[2], bl[3]);
                uint4 al = wf2[alb + k12 * 32];
                mma_bf16(acc[0], al, bh[0], bh[1]);
                mma_bf16(acc[1], al, bh[2], bh[3]);
            }
            __syncthreads();
        }

        // write offsets to smem (co < 18), bias added
        #pragma unroll
        for (int nt = 0; nt < 2; nt++) {
            int loc = ng * 16 + nt * 8 + 2 * t4;
            int coa = mt * 16 + g;
            int cob = coa + 8;
            if (coa < 18) {
                float bb = b2[coa];
                s_off[coa * 64 + loc]     = acc[nt][0] + bb;
                s_off[coa * 64 + loc + 1] = acc[nt][1] + bb;
            }
            if (cob < 18) {
                float bb = b2[cob];
                s_off[cob * 64 + loc]     = acc[nt][2] + bb;
                s_off[cob * 64 + loc + 1] = acc[nt][3] + bb;
            }
        }
    }
    __syncthreads();

    // ===================== Part 2: deform conv2 (R9 core) ====================
    for (int t = tid; t < 576; t += 256) {
        int tap = t >> 6, loc = t & 63;
        float dy = s_off[(tap * 2) * 64 + loc];
        float dx = s_off[(tap * 2 + 1) * 64 + loc];
        float py = (float)(h + tap / 3 - 1) + dy;
        float px = (float)(loc + tap % 3 - 1) + dx;
        float y0f = floorf(py), x0f = floorf(px);
        int y0 = (int)y0f, x0 = (int)x0f;
        s_yx[t] = (y0 << 16) | (x0 & 0xffff);
        s_wyx[t] = make_float2(py - y0f, px - x0f);
    }
    __syncthreads();

    int mw = wid >> 1, nw = wid & 1;
    unsigned vb0 = smb + (unsigned)((nw * 32 + (mlm >> 1) * 8 + rl) * VT_PITCH_B + (mlm & 1) * 16);
    unsigned vb1 = vb0 + 16 * VT_PITCH_B;

    float acc[2][4][4];
    #pragma unroll
    for (int i = 0; i < 2; i++)
        #pragma unroll
        for (int n = 0; n < 4; n++)
            #pragma unroll
            for (int r = 0; r < 4; r++) acc[i][n][r] = 0.f;

    const uint4* wf = (const uint4*)g_wfrag;

    for (int s = 0; s < 3; s++) {
        for (int u = tid; u < 1536; u += 256) {
            int c8 = u & 7, task = u >> 3;
            int tapl = task >> 6, loc = task & 63;
            int t = (s * 3 + tapl) * 64 + loc;
            int yx = s_yx[t];
            int y0 = yx >> 16, x0 = (short)(yx & 0xffff);
            float2 wyx = s_wyx[t];
            float wy = wyx.x, wx = wyx.y;
            float w00 = (1.f - wy) * (1.f - wx), w01 = (1.f - wy) * wx;
            float w10 = wy * (1.f - wx),          w11 = wy * wx;
            bool vy0 = ((unsigned)y0 < 64u), vy1 = ((unsigned)(y0 + 1) < 64u);
            bool vx0 = ((unsigned)x0 < 64u), vx1 = ((unsigned)(x0 + 1) < 64u);
            int ci0 = c8 * 8;
            const float4* p00 = (const float4*)(hb + ((long long)y0 * 64 + x0) * 64 + ci0);
            float4 z = make_float4(0.f, 0.f, 0.f, 0.f);
            bool k00 = vy0 && vx0, k01 = vy0 && vx1, k10 = vy1 && vx0, k11 = vy1 && vx1;
            float4 a00 = k00 ? p00[0]    : z;
            float4 b00 = k00 ? p00[1]    : z;
            float4 a01 = k01 ? p00[16]   : z;
            float4 b01 = k01 ? p00[17]   : z;
            float4 a10 = k10 ? p00[1024] : z;
            float4 b10 = k10 ? p00[1025] : z;
            float4 a11 = k11 ? p00[1040] : z;
            float4 b11 = k11 ? p00[1041] : z;

            float v0 = a00.x * w00 + a01.x * w01 + a10.x * w10 + a11.x * w11;
            float v1 = a00.y * w00 + a01.y * w01 + a10.y * w10 + a11.y * w11;
            float v2_ = a00.z * w00 + a01.z * w01 + a10.z * w10 + a11.z * w11;
            float v3 = a00.w * w00 + a01.w * w01 + a10.w * w10 + a11.w * w11;
            float v4 = b00.x * w00 + b01.x * w01 + b10.x * w10 + b11.x * w11;
            float v5 = b00.y * w00 + b01.y * w01 + b10.y * w10 + b11.y * w11;
            float v6 = b00.z * w00 + b01.z * w01 + b10.z * w10 + b11.z * w11;
            float v7 = b00.w * w00 + b01.w * w01 + b10.w * w10 + b11.w * w11;

            uint4 hi4;
            hi4.x = pack_bf16(v0, v1); hi4.y = pack_bf16(v2_, v3);
            hi4.z = pack_bf16(v4, v5); hi4.w = pack_bf16(v6, v7);
            float r0 = v0  - __uint_as_float(hi4.x << 16);
            float r1 = v1  - __uint_as_float(hi4.x & 0xffff0000u);
            float r2 = v2_ - __uint_as_float(hi4.y << 16);
            float r3 = v3  - __uint_as_float(hi4.y & 0xffff0000u);
            float r4 = v4  - __uint_as_float(hi4.z << 16);
            float r5 = v5  - __uint_as_float(hi4.z & 0xffff0000u);
            float r6 = v6  - __uint_as_float(hi4.w << 16);
            float r7 = v7  - __uint_as_float(hi4.w & 0xffff0000u);
            uint4 lo4;
            lo4.x = pack_bf16(r0, r1); lo4.y = pack_bf16(r2, r3);
            lo4.z = pack_bf16(r4, r5); lo4.w = pack_bf16(r6, r7);

            unsigned off = (unsigned)(loc * VT_PITCH_B + (tapl * 64 + ci0) * 2);
            *(uint4*)(sm + VT_HI_OFF + off) = hi4;
            *(uint4*)(sm + VT_LO_OFF + off) = lo4;
        }
        __syncthreads();

        int ahb0 = ((2 * mw) * 36 + s * 12) * 32 + lane;
        int ahb1 = ahb0 + 36 * 32;
        int alb0 = ahb0 + 288 * 32;
        int alb1 = alb0 + 36 * 32;
        #pragma unroll 1
        for (int k12 = 0; k12 < 12; k12++) {
            uint4 ah0 = wf[ahb0 + k12 * 32];
            uint4 ah1 = wf[ahb1 + k12 * 32];
            unsigned bh0[4], bh1[4], bl0[4], bl1[4];
            ldsm4(bh0[0], bh0[1], bh0[2], bh0[3], vb0 + VT_HI_OFF + (unsigned)(k12 * 32));
            ldsm4(bh1[0], bh1[1], bh1[2], bh1[3], vb1 + VT_HI_OFF + (unsigned)(k12 * 32));
            ldsm4(bl0[0], bl0[1], bl0[2], bl0[3], vb0 + VT_LO_OFF + (unsigned)(k12 * 32));
            ldsm4(bl1[0], bl1[1], bl1[2], bl1[3], vb1 + VT_LO_OFF + (unsigned)(k12 * 32));
            mma_bf16(acc[0][0], ah0, bh0[0], bh0[1]);
            mma_bf16(acc[0][1], ah0, bh0[2], bh0[3]);
            mma_bf16(acc[0][2], ah0, bh1[0], bh1[1]);
            mma_bf16(acc[0][3], ah0, bh1[2], bh1[3]);
            mma_bf16(acc[1][0], ah1, bh0[0], bh0[1]);
            mma_bf16(acc[1][1], ah1, bh0[2], bh0[3]);
            mma_bf16(acc[1][2], ah1, bh1[0], bh1[1]);
            mma_bf16(acc[1][3], ah1, bh1[2], bh1[3]);
            mma_bf16(acc[0][0], ah0, bl0[0], bl0[1]);
            mma_bf16(acc[0][1], ah0, bl0[2], bl0[3]);
            mma_bf16(acc[0][2], ah0, bl1[0], bl1[1]);
            mma_bf16(acc[0][3], ah0, bl1[2], bl1[3]);
            mma_bf16(acc[1][0], ah1, bl0[0], bl0[1]);
            mma_bf16(acc[1][1], ah1, bl0[2], bl0[3]);
            mma_bf16(acc[1][2], ah1, bl1[0], bl1[1]);
            mma_bf16(acc[1][3], ah1, bl1[2], bl1[3]);
            uint4 al0 = wf[alb0 + k12 * 32];
            uint4 al1 = wf[alb1 + k12 * 32];
            mma_bf16(acc[0][0], al0, bh0[0], bh0[1]);
            mma_bf16(acc[0][1], al0, bh0[2], bh0[3]);
            mma_bf16(acc[0][2], al0, bh1[0], bh1[1]);
            mma_bf16(acc[0][3], al0, bh1[2], bh1[3]);
            mma_bf16(acc[1][0], al1, bh0[0], bh0[1]);
            mma_bf16(acc[1][1], al1, bh0[2], bh0[3]);
            mma_bf16(acc[1][2], al1, bh1[0], bh1[1]);
            mma_bf16(acc[1][3], al1, bh1[2], bh1[3]);
        }
        __syncthreads();
    }

    // epilogue: bn+relu+pool partial
    #pragma unroll
    for (int i = 0; i < 2; i++) {
        int coa = (2 * mw + i) * 16 + g;
        int cob = coa + 8;
        float sca = s_scale[coa], bia = s_bias[coa];
        float scb = s_scale[cob], bib = s_bias[cob];
        float sa = 0.f, sb = 0.f;
        #pragma unroll
        for (int nt = 0; nt < 4; nt++) {
            sa += fmaxf(acc[i][nt][0] * sca + bia, 0.f) + fmaxf(acc[i][nt][1] * sca + bia, 0.f);
            sb += fmaxf(acc[i][nt][2] * scb + bib, 0.f) + fmaxf(acc[i][nt][3] * scb + bib, 0.f);
        }
        sa += __shfl_xor_sync(0xffffffffu, sa, 1);
        sa += __shfl_xor_sync(0xffffffffu, sa, 2);
        sb += __shfl_xor_sync(0xffffffffu, sb, 1);
        sb += __shfl_xor_sync(0xffffffffu, sb, 2);
        if (t4 == 0) {
            g_partial[(size_t)(blk * 2 + nw) * 128 + coa] = sa;
            g_partial[(size_t)(blk * 2 + nw) * 128 + cob] = sb;
        }
    }
}

// ---------------- K4a: stage-1 partial reduction -----------------------------
__global__ void __launch_bounds__(128)
k4a_reduce()
{
    int b = blockIdx.x >> 3, seg = blockIdx.x & 7;
    int co = threadIdx.x;
    const float* pb = g_partial + ((size_t)b * 128 + seg * 16) * 128 + co;
    float s0 = 0.f, s1 = 0.f, s2 = 0.f, s3 = 0.f;
    #pragma unroll
    for (int i = 0; i < 4; i++) {
        s0 += pb[(i * 4 + 0) * 128];
        s1 += pb[(i * 4 + 1) * 128];
        s2 += pb[(i * 4 + 2) * 128];
        s3 += pb[(i * 4 + 3) * 128];
    }
    g_pool_seg[(b * 8 + seg) * 128 + co] = (s0 + s1) + (s2 + s3);
}

// ---------------- K4b: final reduce + fc1 + relu + fc2 -----------------------
__global__ void __launch_bounds__(256)
k4b_fc(const float* __restrict__ fc1w, const float* __restrict__ fc1b,
       const float* __restrict__ fc2w, const float* __restrict__ fc2b,
       float* __restrict__ out)
{
    __shared__ float sp[128];
    __shared__ float hid[256];
    int b = blockIdx.x, tid = threadIdx.x;
    if (tid < 128) {
        const float* ps = g_pool_seg + (size_t)b * 8 * 128 + tid;
        float s = 0.f;
        #pragma unroll
        for (int i = 0; i < 8; i++) s += ps[i * 128];
        sp[tid] = s * (1.f / 4096.f);
    }
    __syncthreads();
    {
        float a = fc1b[tid];
        #pragma unroll 8
        for (int j = 0; j < 128; j++) a += fc1w[tid * 128 + j] * sp[j];
        hid[tid] = fmaxf(a, 0.f);
    }
    __syncthreads();
    if (tid < 200) {
        float a = fc2b[tid];
        #pragma unroll 8
        for (int j = 0; j < 256; j++) a += fc2w[tid * 256 + j] * hid[j];
        out[b * 200 + tid] = a;
    }
}

// ---------------- launch -----------------------------------------------------
extern "C" void kernel_launch(void* const* d_in, const int* in_sizes, int n_in,
                              void* d_out, int out_size)
{
    const float* x    = (const float*)d_in[0];
    const float* o1w  = (const float*)d_in[1];
    const float* o1b  = (const float*)d_in[2];
    const float* c1w  = (const float*)d_in[3];
    const float* c1b  = (const float*)d_in[4];
    const float* g1   = (const float*)d_in[5];
    const float* be1  = (const float*)d_in[6];
    const float* m1   = (const float*)d_in[7];
    const float* v1   = (const float*)d_in[8];
    const float* o2w  = (const float*)d_in[9];
    const float* o2b  = (const float*)d_in[10];
    const float* c2w  = (const float*)d_in[11];
    const float* c2b  = (const float*)d_in[12];
    const float* g2   = (const float*)d_in[13];
    const float* be2  = (const float*)d_in[14];
    const float* m2   = (const float*)d_in[15];
    const float* v2   = (const float*)d_in[16];
    const float* f1w  = (const float*)d_in[17];
    const float* f1b  = (const float*)d_in[18];
    const float* f2w  = (const float*)d_in[19];
    const float* f2b  = (const float*)d_in[20];
    float* out = (float*)d_out;

    cudaFuncSetAttribute(k3_fused, cudaFuncAttributeMaxDynamicSharedMemorySize, K3_SMEM);

    k0_prep<<<360, 256>>>(c2w, o2w);
    k1_layer1<<<1024, 128>>>(x, o1w, o1b, c1w, c1b, g1, be1, m1, v1);
    k3_fused<<<2048, 256, K3_SMEM>>>(o2b, c2b, g2, be2, m2, v2);
    k4a_reduce<<<256, 128>>>();
    k4b_fc<<<32, 256>>>(f1w, f1b, f2w, f2b, out);
}

// round 14
// speedup vs baseline: 1.1254x; 1.1254x over previous
#include <cuda_runtime.h>
#include <cuda_bf16.h>
#include <math.h>

#define B_   32
#define HW_  4096
#define C1O  64
#define C2O  128

// ---------------- scratch ----------------------------------------------------
__device__ float g_h1c[(size_t)B_ * HW_ * C1O];        // channel-last h1
__device__ float g_partial[(size_t)4096 * C2O];        // pooled partials (blk*2+nw)
__device__ float g_pool_seg[256 * C2O];                // stage-1 reduced partials
#define WF1_N (2 * 8 * 36 * 128)
#define WF2_N (2 * 2 * 36 * 128)
__device__ unsigned g_wfrag[WF1_N];                    // conv2 A-frags [term][mt][K][lane*4+r]
__device__ unsigned g_wfrag2[WF2_N];                   // off2 A-frags  [term][mt][K][lane*4+r]

typedef unsigned long long ull;

// ---------------- f32x2 helpers ----------------------------------------------
__device__ __forceinline__ ull fma2(ull a, ull b, ull c) {
    ull d; asm("fma.rn.f32x2 %0, %1, %2, %3;" : "=l"(d) : "l"(a), "l"(b), "l"(c)); return d;
}
__device__ __forceinline__ ull dup2(float v) {
    ull d; unsigned r = __float_as_uint(v);
    asm("mov.b64 %0, {%1, %1};" : "=l"(d) : "r"(r)); return d;
}
__device__ __forceinline__ float2 unpack2(ull v) {
    unsigned lo, hi; asm("mov.b64 {%0, %1}, %2;" : "=r"(lo), "=r"(hi) : "l"(v));
    return make_float2(__uint_as_float(lo), __uint_as_float(hi));
}

// ---------------- mma helpers ------------------------------------------------
__device__ __forceinline__ unsigned smem_u32(const void* p) {
    unsigned a;
    asm("{ .reg .u64 t; cvta.to.shared.u64 t, %1; cvt.u32.u64 %0, t; }" : "=r"(a) : "l"(p));
    return a;
}
__device__ __forceinline__ unsigned pack_bf16(float v0, float v1) {  // low=v0, high=v1
    unsigned d; asm("cvt.rn.bf16x2.f32 %0, %1, %2;" : "=r"(d) : "f"(v1), "f"(v0)); return d;
}
__device__ __forceinline__ void ldsm4(unsigned& r0, unsigned& r1, unsigned& r2, unsigned& r3,
                                      unsigned addr) {
    asm volatile("ldmatrix.sync.aligned.m8n8.x4.shared.b16 {%0,%1,%2,%3}, [%4];"
                 : "=r"(r0), "=r"(r1), "=r"(r2), "=r"(r3) : "r"(addr));
}
__device__ __forceinline__ void mma_bf16(float* c, const uint4& a, unsigned b0, unsigned b1) {
    asm volatile(
        "mma.sync.aligned.m16n8k16.row.col.f32.bf16.bf16.f32 "
        "{%0,%1,%2,%3}, {%4,%5,%6,%7}, {%8,%9}, {%0,%1,%2,%3};"
        : "+f"(c[0]), "+f"(c[1]), "+f"(c[2]), "+f"(c[3])
        : "r"(a.x), "r"(a.y), "r"(a.z), "r"(a.w), "r"(b0), "r"(b1));
}

// ---------------- K0: build A-fragment weight images -------------------------
__global__ void k0_prep(const float* __restrict__ cw, const float* __restrict__ w2)
{
    int idx = blockIdx.x * 256 + threadIdx.x;
    if (idx < WF1_N) {
        int r = idx & 3, lane = (idx >> 2) & 31;
        int K = (idx >> 7) % 36;
        int mt = (idx / (128 * 36)) & 7;
        int wt = idx / (128 * 36 * 8);
        int g = lane >> 2, t = lane & 3;
        int co = mt * 16 + g + ((r & 1) ? 8 : 0);
        int kl = 2 * t + ((r & 2) ? 8 : 0);
        float w[2];
        #pragma unroll
        for (int j = 0; j < 2; j++) {
            int e = K * 16 + kl + j;
            int s = e / 192, es = e % 192;
            int tapl = es >> 6, ci = es & 63;
            float wv = cw[co * 576 + ci * 9 + s * 3 + tapl];
            if (wt == 0) w[j] = wv;
            else {
                float hi = __bfloat162float(__float2bfloat16(wv));
                w[j] = wv - hi;
            }
        }
        g_wfrag[idx] = pack_bf16(w[0], w[1]);
    } else if (idx < WF1_N + WF2_N) {
        int i2 = idx - WF1_N;
        int r = i2 & 3, lane = (i2 >> 2) & 31;
        int K = (i2 >> 7) % 36;
        int mt = (i2 / (128 * 36)) & 1;
        int wt = i2 / (128 * 36 * 2);
        int g = lane >> 2, t = lane & 3;
        int co = mt * 16 + g + ((r & 1) ? 8 : 0);
        int kl = 2 * t + ((r & 2) ? 8 : 0);
        float w[2];
        #pragma unroll
        for (int j = 0; j < 2; j++) {
            int e = K * 16 + kl + j;
            int s = e / 192, es = e % 192;
            int tapl = es >> 6, ci = es & 63;
            float wv = (co < 18) ? w2[co * 576 + ci * 9 + s * 3 + tapl] : 0.f;
            if (wt == 0) w[j] = wv;
            else {
                float hi = __bfloat162float(__float2bfloat16(wv));
                w[j] = wv - hi;
            }
        }
        g_wfrag2[i2] = pack_bf16(w[0], w[1]);
    }
}

// ---------------- K1: offset1 + deform conv1 + bn1 + relu (f32x2) ------------
__global__ void __launch_bounds__(128)
k1_layer1(const float* __restrict__ x,
          const float* __restrict__ ow, const float* __restrict__ ob,
          const float* __restrict__ cw, const float* __restrict__ cb,
          const float* __restrict__ g1, const float* __restrict__ be1,
          const float* __restrict__ m1, const float* __restrict__ v1)
{
    __shared__ float s_owT[27 * 20];   // [j][o] pad 20
    __shared__ float s_cwT[27 * 64];   // [j][co]
    __shared__ float s_ob[18];
    __shared__ float s_scale[64], s_bias[64];
    __shared__ float s_out[128 * 65];

    int tid = threadIdx.x;
    for (int i = tid; i < 486; i += 128) {
        int o = i / 27, j = i % 27;
        s_owT[j * 20 + o] = ow[i];
    }
    for (int i = tid; i < 54; i += 128) {          // pad o=18,19
        int j = i % 27, o = 18 + i / 27;
        s_owT[j * 20 + o] = 0.f;
    }
    for (int i = tid; i < 1728; i += 128) {
        int co = i / 27, j = i % 27;
        s_cwT[j * 64 + co] = cw[i];
    }
    if (tid < 18) s_ob[tid] = ob[tid];
    if (tid < 64) {
        float sc = g1[tid] * rsqrtf(v1[tid] + 1e-5f);
        s_scale[tid] = sc;
        s_bias[tid]  = be1[tid] + (cb[tid] - m1[tid]) * sc;
    }
    __syncthreads();

    int lin = blockIdx.x * 128 + tid;
    int b = lin >> 12, hw = lin & 4095, h = hw >> 6, w = hw & 63;
    const float* xb = x + (size_t)b * 3 * 4096;

    float xwin[27];
    #pragma unroll
    for (int ci = 0; ci < 3; ci++)
        #pragma unroll
        for (int kh = 0; kh < 3; kh++)
            #pragma unroll
            for (int kw = 0; kw < 3; kw++) {
                int yy = h + kh - 1, xx = w + kw - 1;
                float val = 0.f;
                if (yy >= 0 && yy < 64 && xx >= 0 && xx < 64)
                    val = xb[ci * 4096 + yy * 64 + xx];
                xwin[ci * 9 + kh * 3 + kw] = val;
            }

    // offsets: 18 outputs as 9(+1 pad) f32x2 pairs
    ull oacc[10];
    #pragma unroll
    for (int p = 0; p < 10; p++) oacc[p] = 0ull;
    #pragma unroll
    for (int j = 0; j < 27; j++) {
        ull vd = dup2(xwin[j]);
        const ulonglong2* wp = (const ulonglong2*)&s_owT[j * 20];
        #pragma unroll
        for (int p = 0; p < 5; p++) {
            ulonglong2 wq = wp[p];
            oacc[p * 2]     = fma2(wq.x, vd, oacc[p * 2]);
            oacc[p * 2 + 1] = fma2(wq.y, vd, oacc[p * 2 + 1]);
        }
    }
    float off[18];
    #pragma unroll
    for (int p = 0; p < 9; p++) {
        float2 f = unpack2(oacc[p]);
        off[2 * p]     = f.x + s_ob[2 * p];
        off[2 * p + 1] = f.y + s_ob[2 * p + 1];
    }

    float v[27];
    #pragma unroll
    for (int tap = 0; tap < 9; tap++) {
        float py = (float)(h + tap / 3 - 1) + off[tap * 2];
        float px = (float)(w + tap % 3 - 1) + off[tap * 2 + 1];
        float y0f = floorf(py), x0f = floorf(px);
        int y0 = (int)y0f, x0 = (int)x0f;
        float wy = py - y0f, wx = px - x0f;
        float w00 = (1.f - wy) * (1.f - wx), w01 = (1.f - wy) * wx;
        float w10 = wy * (1.f - wx),         w11 = wy * wx;
        bool vy0 = ((unsigned)y0 < 64u), vy1 = ((unsigned)(y0 + 1) < 64u);
        bool vx0 = ((unsigned)x0 < 64u), vx1 = ((unsigned)(x0 + 1) < 64u);
        long long i00 = (long long)y0 * 64 + x0;
        #pragma unroll
        for (int ci = 0; ci < 3; ci++) {
            const float* p = xb + ci * 4096;
            float c00 = (vy0 && vx0) ? p[i00]      : 0.f;
            float c01 = (vy0 && vx1) ? p[i00 + 1]  : 0.f;
            float c10 = (vy1 && vx0) ? p[i00 + 64] : 0.f;
            float c11 = (vy1 && vx1) ? p[i00 + 65] : 0.f;
            v[ci * 9 + tap] = c00 * w00 + c01 * w01 + c10 * w10 + c11 * w11;
        }
    }

    // conv outputs: 64 co in two halves of 32 (16 f32x2 pairs each)
    #pragma unroll
    for (int h2 = 0; h2 < 2; h2++) {
        ull acc2[16];
        #pragma unroll
        for (int p = 0; p < 16; p++) acc2[p] = 0ull;
        #pragma unroll
        for (int j = 0; j < 27; j++) {
            ull vd = dup2(v[j]);
            const ulonglong2* wp = (const ulonglong2*)&s_cwT[j * 64 + h2 * 32];
            #pragma unroll
            for (int p = 0; p < 8; p++) {
                ulonglong2 wq = wp[p];
                acc2[p * 2]     = fma2(wq.x, vd, acc2[p * 2]);
                acc2[p * 2 + 1] = fma2(wq.y, vd, acc2[p * 2 + 1]);
            }
        }
        #pragma unroll
        for (int p = 0; p < 16; p++) {
            int co = h2 * 32 + 2 * p;
            float2 f = unpack2(acc2[p]);
            s_out[tid * 65 + co]     = fmaxf(f.x * s_scale[co] + s_bias[co], 0.f);
            s_out[tid * 65 + co + 1] = fmaxf(f.y * s_scale[co + 1] + s_bias[co + 1], 0.f);
        }
    }
    __syncthreads();

    size_t base = (size_t)blockIdx.x * 128 * 64;
    for (int i = tid; i < 8192; i += 128)
        g_h1c[base + i] = s_out[(i >> 6) * 65 + (i & 63)];
}

// ---------------- K3 (fused): offset2 conv + deform conv2 + bn2 + relu + pool
// 2-term chain: Whi*Vhi + Wlo*Vhi (V-lo dropped: per-position rounding noise
// averages out in the 4096-point mean pool; W rounding is systematic -> kept).
#define VT_PITCH_B 400
#define VT_HI_OFF  0
#define CWYX_OFF   25600
#define CYX_OFF    30208
#define SCALE_OFF  32512
#define BIAS_OFF   33024
#define SOFF_OFF   33536          // float[18*64]
#define K3_SMEM    38144

__global__ void __launch_bounds__(256, 3)
k3_fused(const float* __restrict__ b2, const float* __restrict__ cb,
         const float* __restrict__ g2, const float* __restrict__ be2,
         const float* __restrict__ m2, const float* __restrict__ v2)
{
    extern __shared__ char sm[];
    float2* s_wyx  = (float2*)(sm + CWYX_OFF);
    int*    s_yx   = (int*)(sm + CYX_OFF);
    float*  s_scale = (float*)(sm + SCALE_OFF);
    float*  s_bias  = (float*)(sm + BIAS_OFF);
    float*  s_off   = (float*)(sm + SOFF_OFF);
    unsigned smb = smem_u32(sm);

    int tid = threadIdx.x;
    int blk = blockIdx.x;
    int h = blk & 63, b = blk >> 6;

    if (tid < 128) {
        float sc = g2[tid] * rsqrtf(v2[tid] + 1e-5f);
        s_scale[tid] = sc;
        s_bias[tid]  = be2[tid] + (cb[tid] - m2[tid]) * sc;
    }

    const float* hb = g_h1c + (size_t)b * HW_ * C1O;
    int lane = tid & 31, wid = tid >> 5;
    int g = lane >> 2, t4 = lane & 3;
    int mlm = lane >> 3, rl = lane & 7;

    // ===================== Part 1: offsets (k2 machinery) ====================
    {
        int mt = wid & 1, ng = wid >> 1;
        unsigned vb = smb + (unsigned)((ng * 16 + (mlm >> 1) * 8 + rl) * VT_PITCH_B + (mlm & 1) * 16);

        float acc[2][4];
        #pragma unroll
        for (int n = 0; n < 2; n++)
            #pragma unroll
            for (int r = 0; r < 4; r++) acc[n][r] = 0.f;

        const uint4* wf2 = (const uint4*)g_wfrag2;

        for (int s = 0; s < 3; s++) {
            int y = h + s - 1;
            bool rowv = ((unsigned)y < 64u);

            for (int u = tid; u < 1536; u += 256) {
                int c8 = u & 7, task = u >> 3;
                int tapl = task >> 6, loc = task & 63;
                int x = loc + tapl - 1;
                bool valid = rowv && ((unsigned)x < 64u);
                int ci0 = c8 * 8;
                const float4* p = (const float4*)(hb + ((long long)y * 64 + x) * 64 + ci0);
                float4 z = make_float4(0.f, 0.f, 0.f, 0.f);
                float4 va = valid ? p[0] : z;
                float4 vc = valid ? p[1] : z;

                uint4 hi4;
                hi4.x = pack_bf16(va.x, va.y); hi4.y = pack_bf16(va.z, va.w);
                hi4.z = pack_bf16(vc.x, vc.y); hi4.w = pack_bf16(vc.z, vc.w);
                unsigned off = (unsigned)(loc * VT_PITCH_B + (tapl * 64 + ci0) * 2);
                *(uint4*)(sm + VT_HI_OFF + off) = hi4;
            }
            __syncthreads();

            int ahb = (mt * 36 + s * 12) * 32 + lane;
            int alb = ahb + 2 * 36 * 32;
            #pragma unroll 1
            for (int k12 = 0; k12 < 12; k12++) {
                uint4 ah = wf2[ahb + k12 * 32];
                unsigned bh[4];
                ldsm4(bh[0], bh[1], bh[2], bh[3], vb + VT_HI_OFF + (unsigned)(k12 * 32));
                mma_bf16(acc[0], ah, bh[0], bh[1]);
                mma_bf16(acc[1], ah, bh[2], bh[3]);
                uint4 al = wf2[alb + k12 * 32];
                mma_bf16(acc[0], al, bh[0], bh[1]);
                mma_bf16(acc[1], al, bh[2], bh[3]);
            }
            __syncthreads();
        }

        // write offsets to smem (co < 18), bias added
        #pragma unroll
        for (int nt = 0; nt < 2; nt++) {
            int loc = ng * 16 + nt * 8 + 2 * t4;
            int coa = mt * 16 + g;
            int cob = coa + 8;
            if (coa < 18) {
                float bb = b2[coa];
                s_off[coa * 64 + loc]     = acc[nt][0] + bb;
                s_off[coa * 64 + loc + 1] = acc[nt][1] + bb;
            }
            if (cob < 18) {
                float bb = b2[cob];
                s_off[cob * 64 + loc]     = acc[nt][2] + bb;
                s_off[cob * 64 + loc + 1] = acc[nt][3] + bb;
            }
        }
    }
    __syncthreads();

    // ===================== Part 2: deform conv2 ==============================
    for (int t = tid; t < 576; t += 256) {
        int tap = t >> 6, loc = t & 63;
        float dy = s_off[(tap * 2) * 64 + loc];
        float dx = s_off[(tap * 2 + 1) * 64 + loc];
        float py = (float)(h + tap / 3 - 1) + dy;
        float px = (float)(loc + tap % 3 - 1) + dx;
        float y0f = floorf(py), x0f = floorf(px);
        int y0 = (int)y0f, x0 = (int)x0f;
        s_yx[t] = (y0 << 16) | (x0 & 0xffff);
        s_wyx[t] = make_float2(py - y0f, px - x0f);
    }
    __syncthreads();

    int mw = wid >> 1, nw = wid & 1;
    unsigned vb0 = smb + (unsigned)((nw * 32 + (mlm >> 1) * 8 + rl) * VT_PITCH_B + (mlm & 1) * 16);
    unsigned vb1 = vb0 + 16 * VT_PITCH_B;

    float acc[2][4][4];
    #pragma unroll
    for (int i = 0; i < 2; i++)
        #pragma unroll
        for (int n = 0; n < 4; n++)
            #pragma unroll
            for (int r = 0; r < 4; r++) acc[i][n][r] = 0.f;

    const uint4* wf = (const uint4*)g_wfrag;

    for (int s = 0; s < 3; s++) {
        // phase B: sample slab (3 taps x 64 loc x 64 ci) into Vt hi
        for (int u = tid; u < 1536; u += 256) {
            int c8 = u & 7, task = u >> 3;
            int tapl = task >> 6, loc = task & 63;
            int t = (s * 3 + tapl) * 64 + loc;
            int yx = s_yx[t];
            int y0 = yx >> 16, x0 = (short)(yx & 0xffff);
            float2 wyx = s_wyx[t];
            float wy = wyx.x, wx = wyx.y;
            float w00 = (1.f - wy) * (1.f - wx), w01 = (1.f - wy) * wx;
            float w10 = wy * (1.f - wx),          w11 = wy * wx;
            bool vy0 = ((unsigned)y0 < 64u), vy1 = ((unsigned)(y0 + 1) < 64u);
            bool vx0 = ((unsigned)x0 < 64u), vx1 = ((unsigned)(x0 + 1) < 64u);
            int ci0 = c8 * 8;
            const float4* p00 = (const float4*)(hb + ((long long)y0 * 64 + x0) * 64 + ci0);
            float4 z = make_float4(0.f, 0.f, 0.f, 0.f);
            bool k00 = vy0 && vx0, k01 = vy0 && vx1, k10 = vy1 && vx0, k11 = vy1 && vx1;
            float4 a00 = k00 ? p00[0]    : z;
            float4 b00 = k00 ? p00[1]    : z;
            float4 a01 = k01 ? p00[16]   : z;
            float4 b01 = k01 ? p00[17]   : z;
            float4 a10 = k10 ? p00[1024] : z;
            float4 b10 = k10 ? p00[1025] : z;
            float4 a11 = k11 ? p00[1040] : z;
            float4 b11 = k11 ? p00[1041] : z;

            float v0 = a00.x * w00 + a01.x * w01 + a10.x * w10 + a11.x * w11;
            float v1 = a00.y * w00 + a01.y * w01 + a10.y * w10 + a11.y * w11;
            float v2_ = a00.z * w00 + a01.z * w01 + a10.z * w10 + a11.z * w11;
            float v3 = a00.w * w00 + a01.w * w01 + a10.w * w10 + a11.w * w11;
            float v4 = b00.x * w00 + b01.x * w01 + b10.x * w10 + b11.x * w11;
            float v5 = b00.y * w00 + b01.y * w01 + b10.y * w10 + b11.y * w11;
            float v6 = b00.z * w00 + b01.z * w01 + b10.z * w10 + b11.z * w11;
            float v7 = b00.w * w00 + b01.w * w01 + b10.w * w10 + b11.w * w11;

            uint4 hi4;
            hi4.x = pack_bf16(v0, v1); hi4.y = pack_bf16(v2_, v3);
            hi4.z = pack_bf16(v4, v5); hi4.w = pack_bf16(v6, v7);
            unsigned off = (unsigned)(loc * VT_PITCH_B + (tapl * 64 + ci0) * 2);
            *(uint4*)(sm + VT_HI_OFF + off) = hi4;
        }
        __syncthreads();

        // fused MMA: per kstep do Ahi*Bhi + Alo*Bhi
        int ahb0 = ((2 * mw) * 36 + s * 12) * 32 + lane;
        int ahb1 = ahb0 + 36 * 32;
        int alb0 = ahb0 + 288 * 32;
        int alb1 = alb0 + 36 * 32;
        #pragma unroll 1
        for (int k12 = 0; k12 < 12; k12++) {
            uint4 ah0 = wf[ahb0 + k12 * 32];
            uint4 ah1 = wf[ahb1 + k12 * 32];
            unsigned bh0[4], bh1[4];
            ldsm4(bh0[0], bh0[1], bh0[2], bh0[3], vb0 + VT_HI_OFF + (unsigned)(k12 * 32));
            ldsm4(bh1[0], bh1[1], bh1[2], bh1[3], vb1 + VT_HI_OFF + (unsigned)(k12 * 32));
            // term 0: Ahi * Bhi
            mma_bf16(acc[0][0], ah0, bh0[0], bh0[1]);
            mma_bf16(acc[0][1], ah0, bh0[2], bh0[3]);
            mma_bf16(acc[0][2], ah0, bh1[0], bh1[1]);
            mma_bf16(acc[0][3], ah0, bh1[2], bh1[3]);
            mma_bf16(acc[1][0], ah1, bh0[0], bh0[1]);
            mma_bf16(acc[1][1], ah1, bh0[2], bh0[3]);
            mma_bf16(acc[1][2], ah1, bh1[0], bh1[1]);
            mma_bf16(acc[1][3], ah1, bh1[2], bh1[3]);
            // term 1: Alo * Bhi
            uint4 al0 = wf[alb0 + k12 * 32];
            uint4 al1 = wf[alb1 + k12 * 32];
            mma_bf16(acc[0][0], al0, bh0[0], bh0[1]);
            mma_bf16(acc[0][1], al0, bh0[2], bh0[3]);
            mma_bf16(acc[0][2], al0, bh1[0], bh1[1]);
            mma_bf16(acc[0][3], al0, bh1[2], bh1[3]);
            mma_bf16(acc[1][0], al1, bh0[0], bh0[1]);
            mma_bf16(acc[1][1], al1, bh0[2], bh0[3]);
            mma_bf16(acc[1][2], al1, bh1[0], bh1[1]);
            mma_bf16(acc[1][3], al1, bh1[2], bh1[3]);
        }
        __syncthreads();
    }

    // epilogue: bn+relu+pool partial
    #pragma unroll
    for (int i = 0; i < 2; i++) {
        int coa = (2 * mw + i) * 16 + g;
        int cob = coa + 8;
        float sca = s_scale[coa], bia = s_bias[coa];
        float scb = s_scale[cob], bib = s_bias[cob];
        float sa = 0.f, sb = 0.f;
        #pragma unroll
        for (int nt = 0; nt < 4; nt++) {
            sa += fmaxf(acc[i][nt][0] * sca + bia, 0.f) + fmaxf(acc[i][nt][1] * sca + bia, 0.f);
            sb += fmaxf(acc[i][nt][2] * scb + bib, 0.f) + fmaxf(acc[i][nt][3] * scb + bib, 0.f);
        }
        sa += __shfl_xor_sync(0xffffffffu, sa, 1);
        sa += __shfl_xor_sync(0xffffffffu, sa, 2);
        sb += __shfl_xor_sync(0xffffffffu, sb, 1);
        sb += __shfl_xor_sync(0xffffffffu, sb, 2);
        if (t4 == 0) {
            g_partial[(size_t)(blk * 2 + nw) * 128 + coa] = sa;
            g_partial[(size_t)(blk * 2 + nw) * 128 + cob] = sb;
        }
    }
}

// ---------------- K4a: stage-1 partial reduction -----------------------------
__global__ void __launch_bounds__(128)
k4a_reduce()
{
    int b = blockIdx.x >> 3, seg = blockIdx.x & 7;
    int co = threadIdx.x;
    const float* pb = g_partial + ((size_t)b * 128 + seg * 16) * 128 + co;
    float s0 = 0.f, s1 = 0.f, s2 = 0.f, s3 = 0.f;
    #pragma unroll
    for (int i = 0; i < 4; i++) {
        s0 += pb[(i * 4 + 0) * 128];
        s1 += pb[(i * 4 + 1) * 128];
        s2 += pb[(i * 4 + 2) * 128];
        s3 += pb[(i * 4 + 3) * 128];
    }
    g_pool_seg[(b * 8 + seg) * 128 + co] = (s0 + s1) + (s2 + s3);
}

// ---------------- K4b: final reduce + fc1 + relu + fc2 -----------------------
__global__ void __launch_bounds__(256)
k4b_fc(const float* __restrict__ fc1w, const float* __restrict__ fc1b,
       const float* __restrict__ fc2w, const float* __restrict__ fc2b,
       float* __restrict__ out)
{
    __shared__ float sp[128];
    __shared__ float hid[256];
    int b = blockIdx.x, tid = threadIdx.x;
    if (tid < 128) {
        const float* ps = g_pool_seg + (size_t)b * 8 * 128 + tid;
        float s = 0.f;
        #pragma unroll
        for (int i = 0; i < 8; i++) s += ps[i * 128];
        sp[tid] = s * (1.f / 4096.f);
    }
    __syncthreads();
    {
        float a = fc1b[tid];
        #pragma unroll 8
        for (int j = 0; j < 128; j++) a += fc1w[tid * 128 + j] * sp[j];
        hid[tid] = fmaxf(a, 0.f);
    }
    __syncthreads();
    if (tid < 200) {
        float a = fc2b[tid];
        #pragma unroll 8
        for (int j = 0; j < 256; j++) a += fc2w[tid * 256 + j] * hid[j];
        out[b * 200 + tid] = a;
    }
}

// ---------------- launch -----------------------------------------------------
extern "C" void kernel_launch(void* const* d_in, const int* in_sizes, int n_in,
                              void* d_out, int out_size)
{
    const float* x    = (const float*)d_in[0];
    const float* o1w  = (const float*)d_in[1];
    const float* o1b  = (const float*)d_in[2];
    const float* c1w  = (const float*)d_in[3];
    const float* c1b  = (const float*)d_in[4];
    const float* g1   = (const float*)d_in[5];
    const float* be1  = (const float*)d_in[6];
    const float* m1   = (const float*)d_in[7];
    const float* v1   = (const float*)d_in[8];
    const float* o2w  = (const float*)d_in[9];
    const float* o2b  = (const float*)d_in[10];
    const float* c2w  = (const float*)d_in[11];
    const float* c2b  = (const float*)d_in[12];
    const float* g2   = (const float*)d_in[13];
    const float* be2  = (const float*)d_in[14];
    const float* m2   = (const float*)d_in[15];
    const float* v2   = (const float*)d_in[16];
    const float* f1w  = (const float*)d_in[17];
    const float* f1b  = (const float*)d_in[18];
    const float* f2w  = (const float*)d_in[19];
    const float* f2b  = (const float*)d_in[20];
    float* out = (float*)d_out;

    cudaFuncSetAttribute(k3_fused, cudaFuncAttributeMaxDynamicSharedMemorySize, K3_SMEM);

    k0_prep<<<360, 256>>>(c2w, o2w);
    k1_layer1<<<1024, 128>>>(x, o1w, o1b, c1w, c1b, g1, be1, m1, v1);
    k3_fused<<<2048, 256, K3_SMEM>>>(o2b, c2b, g2, be2, m2, v2);
    k4a_reduce<<<256, 128>>>();
    k4b_fc<<<32, 256>>>(f1w, f1b, f2w, f2b, out);
}

// round 15
// speedup vs baseline: 1.1564x; 1.0276x over previous
#include <cuda_runtime.h>
#include <cuda_bf16.h>
#include <math.h>

#define B_   32
#define HW_  4096
#define C1O  64
#define C2O  128

// ---------------- scratch ----------------------------------------------------
__device__ float g_h1c[(size_t)B_ * HW_ * C1O];        // channel-last h1
__device__ float g_partial[(size_t)4096 * C2O];        // pooled partials (blk*2+nw)
__device__ float g_pool_seg[256 * C2O];                // stage-1 reduced partials
#define WF1_N (2 * 8 * 36 * 128)
#define WF2_N (2 * 2 * 36 * 128)
#define WF3_N (2 * 4 * 2 * 128)
__device__ unsigned g_wfrag[WF1_N];                    // conv2 A-frags [term][mt][K][lane*4+r]
__device__ unsigned g_wfrag2[WF2_N];                   // off2 A-frags
__device__ unsigned g_wfrag1[WF3_N];                   // conv1 A-frags [term][mt][K][lane*4+r]

typedef unsigned long long ull;

// ---------------- f32x2 helpers ----------------------------------------------
__device__ __forceinline__ ull fma2(ull a, ull b, ull c) {
    ull d; asm("fma.rn.f32x2 %0, %1, %2, %3;" : "=l"(d) : "l"(a), "l"(b), "l"(c)); return d;
}
__device__ __forceinline__ ull dup2(float v) {
    ull d; unsigned r = __float_as_uint(v);
    asm("mov.b64 %0, {%1, %1};" : "=l"(d) : "r"(r)); return d;
}
__device__ __forceinline__ float2 unpack2(ull v) {
    unsigned lo, hi; asm("mov.b64 {%0, %1}, %2;" : "=r"(lo), "=r"(hi) : "l"(v));
    return make_float2(__uint_as_float(lo), __uint_as_float(hi));
}

// ---------------- mma helpers ------------------------------------------------
__device__ __forceinline__ unsigned smem_u32(const void* p) {
    unsigned a;
    asm("{ .reg .u64 t; cvta.to.shared.u64 t, %1; cvt.u32.u64 %0, t; }" : "=r"(a) : "l"(p));
    return a;
}
__device__ __forceinline__ unsigned pack_bf16(float v0, float v1) {  // low=v0, high=v1
    unsigned d; asm("cvt.rn.bf16x2.f32 %0, %1, %2;" : "=r"(d) : "f"(v1), "f"(v0)); return d;
}
__device__ __forceinline__ unsigned short bf16_1(float v) {
    __nv_bfloat16 b = __float2bfloat16(v);
    return *(unsigned short*)&b;
}
__device__ __forceinline__ void ldsm4(unsigned& r0, unsigned& r1, unsigned& r2, unsigned& r3,
                                      unsigned addr) {
    asm volatile("ldmatrix.sync.aligned.m8n8.x4.shared.b16 {%0,%1,%2,%3}, [%4];"
                 : "=r"(r0), "=r"(r1), "=r"(r2), "=r"(r3) : "r"(addr));
}
__device__ __forceinline__ void mma_bf16(float* c, const uint4& a, unsigned b0, unsigned b1) {
    asm volatile(
        "mma.sync.aligned.m16n8k16.row.col.f32.bf16.bf16.f32 "
        "{%0,%1,%2,%3}, {%4,%5,%6,%7}, {%8,%9}, {%0,%1,%2,%3};"
        : "+f"(c[0]), "+f"(c[1]), "+f"(c[2]), "+f"(c[3])
        : "r"(a.x), "r"(a.y), "r"(a.z), "r"(a.w), "r"(b0), "r"(b1));
}

// ---------------- K0: build A-fragment weight images -------------------------
__global__ void k0_prep(const float* __restrict__ cw, const float* __restrict__ w2,
                        const float* __restrict__ c1w)
{
    int idx = blockIdx.x * 256 + threadIdx.x;
    if (idx < WF1_N) {
        int r = idx & 3, lane = (idx >> 2) & 31;
        int K = (idx >> 7) % 36;
        int mt = (idx / (128 * 36)) & 7;
        int wt = idx / (128 * 36 * 8);
        int g = lane >> 2, t = lane & 3;
        int co = mt * 16 + g + ((r & 1) ? 8 : 0);
        int kl = 2 * t + ((r & 2) ? 8 : 0);
        float w[2];
        #pragma unroll
        for (int j = 0; j < 2; j++) {
            int e = K * 16 + kl + j;
            int s = e / 192, es = e % 192;
            int tapl = es >> 6, ci = es & 63;
            float wv = cw[co * 576 + ci * 9 + s * 3 + tapl];
            if (wt == 0) w[j] = wv;
            else {
                float hi = __bfloat162float(__float2bfloat16(wv));
                w[j] = wv - hi;
            }
        }
        g_wfrag[idx] = pack_bf16(w[0], w[1]);
    } else if (idx < WF1_N + WF2_N) {
        int i2 = idx - WF1_N;
        int r = i2 & 3, lane = (i2 >> 2) & 31;
        int K = (i2 >> 7) % 36;
        int mt = (i2 / (128 * 36)) & 1;
        int wt = i2 / (128 * 36 * 2);
        int g = lane >> 2, t = lane & 3;
        int co = mt * 16 + g + ((r & 1) ? 8 : 0);
        int kl = 2 * t + ((r & 2) ? 8 : 0);
        float w[2];
        #pragma unroll
        for (int j = 0; j < 2; j++) {
            int e = K * 16 + kl + j;
            int s = e / 192, es = e % 192;
            int tapl = es >> 6, ci = es & 63;
            float wv = (co < 18) ? w2[co * 576 + ci * 9 + s * 3 + tapl] : 0.f;
            if (wt == 0) w[j] = wv;
            else {
                float hi = __bfloat162float(__float2bfloat16(wv));
                w[j] = wv - hi;
            }
        }
        g_wfrag2[i2] = pack_bf16(w[0], w[1]);
    } else if (idx < WF1_N + WF2_N + WF3_N) {
        int i3 = idx - WF1_N - WF2_N;
        int r = i3 & 3, lane = (i3 >> 2) & 31;
        int K = (i3 >> 7) & 1;
        int mt = (i3 / (128 * 2)) & 3;
        int wt = i3 / (128 * 2 * 4);
        int g = lane >> 2, t = lane & 3;
        int co = mt * 16 + g + ((r & 1) ? 8 : 0);
        int kl = 2 * t + ((r & 2) ? 8 : 0);
        float w[2];
        #pragma unroll
        for (int j = 0; j < 2; j++) {
            int e = K * 16 + kl + j;
            float wv = 0.f;
            if (e < 27) {
                int tap = e / 3, ci = e % 3;
                wv = c1w[co * 27 + ci * 9 + tap];
            }
            if (wt == 0) w[j] = wv;
            else {
                float hi = __bfloat162float(__float2bfloat16(wv));
                w[j] = wv - hi;
            }
        }
        g_wfrag1[i3] = pack_bf16(w[0], w[1]);
    }
}

// ---------------- K1: offset1 + deform conv1 + bn1 + relu (mma) --------------
// CTA = (b, h), 64 locs. Offsets scalar (64 threads), sampling cooperative,
// conv1 as mma D[64co x 64loc] K=32 (e = tap*3+ci, pad 27->32), 2-term W chain.
#define VT1_PITCH 80

__global__ void __launch_bounds__(256)
k1_mma(const float* __restrict__ x,
       const float* __restrict__ ow, const float* __restrict__ ob,
       const float* __restrict__ cb, const float* __restrict__ g1,
       const float* __restrict__ be1, const float* __restrict__ m1,
       const float* __restrict__ v1)
{
    __shared__ float s_owT[27 * 20];
    __shared__ float s_ob[18];
    __shared__ float s_off1[18 * 64];
    __shared__ __align__(16) char s_vt[64 * VT1_PITCH];
    __shared__ float s_scale[64], s_bias[64];
    __shared__ float s_out[64 * 65];

    int tid = threadIdx.x;
    int blk = blockIdx.x;
    int h = blk & 63, b = blk >> 6;
    int lane = tid & 31, wid = tid >> 5;

    for (int i = tid; i < 486; i += 256) { int o = i / 27, j = i % 27; s_owT[j * 20 + o] = ow[i]; }
    for (int i = tid; i < 54; i += 256)  { int j = i % 27, o = 18 + i / 27; s_owT[j * 20 + o] = 0.f; }
    if (tid < 18) s_ob[tid] = ob[tid];
    if (tid < 64) {
        float sc = g1[tid] * rsqrtf(v1[tid] + 1e-5f);
        s_scale[tid] = sc;
        s_bias[tid]  = be1[tid] + (cb[tid] - m1[tid]) * sc;
    }
    for (int i = tid; i < (64 * VT1_PITCH) / 16; i += 256)
        ((uint4*)s_vt)[i] = make_uint4(0, 0, 0, 0);
    __syncthreads();

    const float* xb = x + (size_t)b * 3 * 4096;

    // offsets: one loc per thread (tid < 64)
    if (tid < 64) {
        int w = tid;
        float xwin[27];
        #pragma unroll
        for (int ci = 0; ci < 3; ci++)
            #pragma unroll
            for (int kh = 0; kh < 3; kh++)
                #pragma unroll
                for (int kw = 0; kw < 3; kw++) {
                    int yy = h + kh - 1, xx = w + kw - 1;
                    float val = 0.f;
                    if (yy >= 0 && yy < 64 && xx >= 0 && xx < 64)
                        val = xb[ci * 4096 + yy * 64 + xx];
                    xwin[ci * 9 + kh * 3 + kw] = val;
                }
        ull oacc[10];
        #pragma unroll
        for (int p = 0; p < 10; p++) oacc[p] = 0ull;
        #pragma unroll
        for (int j = 0; j < 27; j++) {
            ull vd = dup2(xwin[j]);
            const ulonglong2* wp = (const ulonglong2*)&s_owT[j * 20];
            #pragma unroll
            for (int p = 0; p < 5; p++) {
                ulonglong2 wq = wp[p];
                oacc[p * 2]     = fma2(wq.x, vd, oacc[p * 2]);
                oacc[p * 2 + 1] = fma2(wq.y, vd, oacc[p * 2 + 1]);
            }
        }
        #pragma unroll
        for (int p = 0; p < 9; p++) {
            float2 f = unpack2(oacc[p]);
            s_off1[(2 * p) * 64 + w]     = f.x + s_ob[2 * p];
            s_off1[(2 * p + 1) * 64 + w] = f.y + s_ob[2 * p + 1];
        }
    }
    __syncthreads();

    // cooperative bilinear sampling: 576 tasks (tap, loc), 3 ci each
    for (int u = tid; u < 576; u += 256) {
        int tap = u >> 6, loc = u & 63;
        float dy = s_off1[(tap * 2) * 64 + loc];
        float dx = s_off1[(tap * 2 + 1) * 64 + loc];
        float py = (float)(h + tap / 3 - 1) + dy;
        float px = (float)(loc + tap % 3 - 1) + dx;
        float y0f = floorf(py), x0f = floorf(px);
        int y0 = (int)y0f, x0 = (int)x0f;
        float wy = py - y0f, wx = px - x0f;
        float w00 = (1.f - wy) * (1.f - wx), w01 = (1.f - wy) * wx;
        float w10 = wy * (1.f - wx),         w11 = wy * wx;
        bool vy0 = ((unsigned)y0 < 64u), vy1 = ((unsigned)(y0 + 1) < 64u);
        bool vx0 = ((unsigned)x0 < 64u), vx1 = ((unsigned)(x0 + 1) < 64u);
        bool k00 = vy0 && vx0, k01 = vy0 && vx1, k10 = vy1 && vx0, k11 = vy1 && vx1;
        long long i00 = (long long)y0 * 64 + x0;
        unsigned short* vd = (unsigned short*)(s_vt + loc * VT1_PITCH + (tap * 3) * 2);
        #pragma unroll
        for (int ci = 0; ci < 3; ci++) {
            const float* p = xb + ci * 4096;
            float c00 = k00 ? p[i00]      : 0.f;
            float c01 = k01 ? p[i00 + 1]  : 0.f;
            float c10 = k10 ? p[i00 + 64] : 0.f;
            float c11 = k11 ? p[i00 + 65] : 0.f;
            vd[ci] = bf16_1(c00 * w00 + c01 * w01 + c10 * w10 + c11 * w11);
        }
    }
    __syncthreads();

    // mma: D[64co x 64loc], K=32 (2 ksteps), terms Whi + Wlo (V hi only)
    int mw = wid >> 1, nw = wid & 1;
    int mlm = lane >> 3, rl = lane & 7;
    unsigned smv = smem_u32(s_vt);
    unsigned vb0 = smv + (unsigned)((nw * 32 + (mlm >> 1) * 8 + rl) * VT1_PITCH + (mlm & 1) * 16);
    unsigned vb1 = vb0 + 16 * VT1_PITCH;

    float acc[4][4];
    #pragma unroll
    for (int n = 0; n < 4; n++)
        #pragma unroll
        for (int r = 0; r < 4; r++) acc[n][r] = 0.f;

    const uint4* wf1 = (const uint4*)g_wfrag1;
    #pragma unroll
    for (int k = 0; k < 2; k++) {
        uint4 ah = wf1[((0 * 4 + mw) * 2 + k) * 32 + lane];
        uint4 al = wf1[((1 * 4 + mw) * 2 + k) * 32 + lane];
        unsigned b0[4], b1[4];
        ldsm4(b0[0], b0[1], b0[2], b0[3], vb0 + (unsigned)(k * 32));
        ldsm4(b1[0], b1[1], b1[2], b1[3], vb1 + (unsigned)(k * 32));
        mma_bf16(acc[0], ah, b0[0], b0[1]);
        mma_bf16(acc[1], ah, b0[2], b0[3]);
        mma_bf16(acc[2], ah, b1[0], b1[1]);
        mma_bf16(acc[3], ah, b1[2], b1[3]);
        mma_bf16(acc[0], al, b0[0], b0[1]);
        mma_bf16(acc[1], al, b0[2], b0[3]);
        mma_bf16(acc[2], al, b1[0], b1[1]);
        mma_bf16(acc[3], al, b1[2], b1[3]);
    }

    // epilogue: bn + relu -> s_out -> coalesced channel-last store
    int g_ = lane >> 2, t4 = lane & 3;
    int coa = mw * 16 + g_, cob = coa + 8;
    float sca = s_scale[coa], bia = s_bias[coa];
    float scb = s_scale[cob], bib = s_bias[cob];
    #pragma unroll
    for (int nt = 0; nt < 4; nt++) {
        int loc = nw * 32 + nt * 8 + 2 * t4;
        s_out[loc * 65 + coa]       = fmaxf(acc[nt][0] * sca + bia, 0.f);
        s_out[(loc + 1) * 65 + coa] = fmaxf(acc[nt][1] * sca + bia, 0.f);
        s_out[loc * 65 + cob]       = fmaxf(acc[nt][2] * scb + bib, 0.f);
        s_out[(loc + 1) * 65 + cob] = fmaxf(acc[nt][3] * scb + bib, 0.f);
    }
    __syncthreads();

    size_t base = (size_t)blk * 4096;
    for (int i = tid; i < 4096; i += 256)
        g_h1c[base + i] = s_out[(i >> 6) * 65 + (i & 63)];
}

// ---------------- K3 (fused): offset2 conv + deform conv2 + bn2 + relu + pool
// 2-term chain: Whi*Vhi + Wlo*Vhi.
#define VT_PITCH_B 400
#define VT_HI_OFF  0
#define CWYX_OFF   25600
#define CYX_OFF    30208
#define SCALE_OFF  32512
#define BIAS_OFF   33024
#define SOFF_OFF   33536          // float[18*64]
#define K3_SMEM    38144

__global__ void __launch_bounds__(256, 3)
k3_fused(const float* __restrict__ b2, const float* __restrict__ cb,
         const float* __restrict__ g2, const float* __restrict__ be2,
         const float* __restrict__ m2, const float* __restrict__ v2)
{
    extern __shared__ char sm[];
    float2* s_wyx  = (float2*)(sm + CWYX_OFF);
    int*    s_yx   = (int*)(sm + CYX_OFF);
    float*  s_scale = (float*)(sm + SCALE_OFF);
    float*  s_bias  = (float*)(sm + BIAS_OFF);
    float*  s_off   = (float*)(sm + SOFF_OFF);
    unsigned smb = smem_u32(sm);

    int tid = threadIdx.x;
    int blk = blockIdx.x;
    int h = blk & 63, b = blk >> 6;

    if (tid < 128) {
        float sc = g2[tid] * rsqrtf(v2[tid] + 1e-5f);
        s_scale[tid] = sc;
        s_bias[tid]  = be2[tid] + (cb[tid] - m2[tid]) * sc;
    }

    const float* hb = g_h1c + (size_t)b * HW_ * C1O;
    int lane = tid & 31, wid = tid >> 5;
    int g = lane >> 2, t4 = lane & 3;
    int mlm = lane >> 3, rl = lane & 7;

    // ===================== Part 1: offsets ====================
    {
        int mt = wid & 1, ng = wid >> 1;
        unsigned vb = smb + (unsigned)((ng * 16 + (mlm >> 1) * 8 + rl) * VT_PITCH_B + (mlm & 1) * 16);

        float acc[2][4];
        #pragma unroll
        for (int n = 0; n < 2; n++)
            #pragma unroll
            for (int r = 0; r < 4; r++) acc[n][r] = 0.f;

        const uint4* wf2 = (const uint4*)g_wfrag2;

        for (int s = 0; s < 3; s++) {
            int y = h + s - 1;
            bool rowv = ((unsigned)y < 64u);

            for (int u = tid; u < 1536; u += 256) {
                int c8 = u & 7, task = u >> 3;
                int tapl = task >> 6, loc = task & 63;
                int x = loc + tapl - 1;
                bool valid = rowv && ((unsigned)x < 64u);
                int ci0 = c8 * 8;
                const float4* p = (const float4*)(hb + ((long long)y * 64 + x) * 64 + ci0);
                float4 z = make_float4(0.f, 0.f, 0.f, 0.f);
                float4 va = valid ? p[0] : z;
                float4 vc = valid ? p[1] : z;

                uint4 hi4;
                hi4.x = pack_bf16(va.x, va.y); hi4.y = pack_bf16(va.z, va.w);
                hi4.z = pack_bf16(vc.x, vc.y); hi4.w = pack_bf16(vc.z, vc.w);
                unsigned off = (unsigned)(loc * VT_PITCH_B + (tapl * 64 + ci0) * 2);
                *(uint4*)(sm + VT_HI_OFF + off) = hi4;
            }
            __syncthreads();

            int ahb = (mt * 36 + s * 12) * 32 + lane;
            int alb = ahb + 2 * 36 * 32;
            #pragma unroll 1
            for (int k12 = 0; k12 < 12; k12++) {
                uint4 ah = wf2[ahb + k12 * 32];
                unsigned bh[4];
                ldsm4(bh[0], bh[1], bh[2], bh[3], vb + VT_HI_OFF + (unsigned)(k12 * 32));
                mma_bf16(acc[0], ah, bh[0], bh[1]);
                mma_bf16(acc[1], ah, bh[2], bh[3]);
                uint4 al = wf2[alb + k12 * 32];
                mma_bf16(acc[0], al, bh[0], bh[1]);
                mma_bf16(acc[1], al, bh[2], bh[3]);
            }
            __syncthreads();
        }

        #pragma unroll
        for (int nt = 0; nt < 2; nt++) {
            int loc = ng * 16 + nt * 8 + 2 * t4;
            int coa = mt * 16 + g;
            int cob = coa + 8;
            if (coa < 18) {
                float bb = b2[coa];
                s_off[coa * 64 + loc]     = acc[nt][0] + bb;
                s_off[coa * 64 + loc + 1] = acc[nt][1] + bb;
            }
            if (cob < 18) {
                float bb = b2[cob];
                s_off[cob * 64 + loc]     = acc[nt][2] + bb;
                s_off[cob * 64 + loc + 1] = acc[nt][3] + bb;
            }
        }
    }
    __syncthreads();

    // ===================== Part 2: deform conv2 ==============================
    for (int t = tid; t < 576; t += 256) {
        int tap = t >> 6, loc = t & 63;
        float dy = s_off[(tap * 2) * 64 + loc];
        float dx = s_off[(tap * 2 + 1) * 64 + loc];
        float py = (float)(h + tap / 3 - 1) + dy;
        float px = (float)(loc + tap % 3 - 1) + dx;
        float y0f = floorf(py), x0f = floorf(px);
        int y0 = (int)y0f, x0 = (int)x0f;
        s_yx[t] = (y0 << 16) | (x0 & 0xffff);
        s_wyx[t] = make_float2(py - y0f, px - x0f);
    }
    __syncthreads();

    int mw = wid >> 1, nw = wid & 1;
    unsigned vb0 = smb + (unsigned)((nw * 32 + (mlm >> 1) * 8 + rl) * VT_PITCH_B + (mlm & 1) * 16);
    unsigned vb1 = vb0 + 16 * VT_PITCH_B;

    float acc[2][4][4];
    #pragma unroll
    for (int i = 0; i < 2; i++)
        #pragma unroll
        for (int n = 0; n < 4; n++)
            #pragma unroll
            for (int r = 0; r < 4; r++) acc[i][n][r] = 0.f;

    const uint4* wf = (const uint4*)g_wfrag;

    for (int s = 0; s < 3; s++) {
        for (int u = tid; u < 1536; u += 256) {
            int c8 = u & 7, task = u >> 3;
            int tapl = task >> 6, loc = task & 63;
            int t = (s * 3 + tapl) * 64 + loc;
            int yx = s_yx[t];
            int y0 = yx >> 16, x0 = (short)(yx & 0xffff);
            float2 wyx = s_wyx[t];
            float wy = wyx.x, wx = wyx.y;
            float w00 = (1.f - wy) * (1.f - wx), w01 = (1.f - wy) * wx;
            float w10 = wy * (1.f - wx),          w11 = wy * wx;
            bool vy0 = ((unsigned)y0 < 64u), vy1 = ((unsigned)(y0 + 1) < 64u);
            bool vx0 = ((unsigned)x0 < 64u), vx1 = ((unsigned)(x0 + 1) < 64u);
            int ci0 = c8 * 8;
            const float4* p00 = (const float4*)(hb + ((long long)y0 * 64 + x0) * 64 + ci0);
            float4 z = make_float4(0.f, 0.f, 0.f, 0.f);
            bool k00 = vy0 && vx0, k01 = vy0 && vx1, k10 = vy1 && vx0, k11 = vy1 && vx1;
            float4 a00 = k00 ? p00[0]    : z;
            float4 b00 = k00 ? p00[1]    : z;
            float4 a01 = k01 ? p00[16]   : z;
            float4 b01 = k01 ? p00[17]   : z;
            float4 a10 = k10 ? p00[1024] : z;
            float4 b10 = k10 ? p00[1025] : z;
            float4 a11 = k11 ? p00[1040] : z;
            float4 b11 = k11 ? p00[1041] : z;

            float v0 = a00.x * w00 + a01.x * w01 + a10.x * w10 + a11.x * w11;
            float v1 = a00.y * w00 + a01.y * w01 + a10.y * w10 + a11.y * w11;
            float v2_ = a00.z * w00 + a01.z * w01 + a10.z * w10 + a11.z * w11;
            float v3 = a00.w * w00 + a01.w * w01 + a10.w * w10 + a11.w * w11;
            float v4 = b00.x * w00 + b01.x * w01 + b10.x * w10 + b11.x * w11;
            float v5 = b00.y * w00 + b01.y * w01 + b10.y * w10 + b11.y * w11;
            float v6 = b00.z * w00 + b01.z * w01 + b10.z * w10 + b11.z * w11;
            float v7 = b00.w * w00 + b01.w * w01 + b10.w * w10 + b11.w * w11;

            uint4 hi4;
            hi4.x = pack_bf16(v0, v1); hi4.y = pack_bf16(v2_, v3);
            hi4.z = pack_bf16(v4, v5); hi4.w = pack_bf16(v6, v7);
            unsigned off = (unsigned)(loc * VT_PITCH_B + (tapl * 64 + ci0) * 2);
            *(uint4*)(sm + VT_HI_OFF + off) = hi4;
        }
        __syncthreads();

        int ahb0 = ((2 * mw) * 36 + s * 12) * 32 + lane;
        int ahb1 = ahb0 + 36 * 32;
        int alb0 = ahb0 + 288 * 32;
        int alb1 = alb0 + 36 * 32;
        #pragma unroll 1
        for (int k12 = 0; k12 < 12; k12++) {
            uint4 ah0 = wf[ahb0 + k12 * 32];
            uint4 ah1 = wf[ahb1 + k12 * 32];
            unsigned bh0[4], bh1[4];
            ldsm4(bh0[0], bh0[1], bh0[2], bh0[3], vb0 + VT_HI_OFF + (unsigned)(k12 * 32));
            ldsm4(bh1[0], bh1[1], bh1[2], bh1[3], vb1 + VT_HI_OFF + (unsigned)(k12 * 32));
            mma_bf16(acc[0][0], ah0, bh0[0], bh0[1]);
            mma_bf16(acc[0][1], ah0, bh0[2], bh0[3]);
            mma_bf16(acc[0][2], ah0, bh1[0], bh1[1]);
            mma_bf16(acc[0][3], ah0, bh1[2], bh1[3]);
            mma_bf16(acc[1][0], ah1, bh0[0], bh0[1]);
            mma_bf16(acc[1][1], ah1, bh0[2], bh0[3]);
            mma_bf16(acc[1][2], ah1, bh1[0], bh1[1]);
            mma_bf16(acc[1][3], ah1, bh1[2], bh1[3]);
            uint4 al0 = wf[alb0 + k12 * 32];
            uint4 al1 = wf[alb1 + k12 * 32];
            mma_bf16(acc[0][0], al0, bh0[0], bh0[1]);
            mma_bf16(acc[0][1], al0, bh0[2], bh0[3]);
            mma_bf16(acc[0][2], al0, bh1[0], bh1[1]);
            mma_bf16(acc[0][3], al0, bh1[2], bh1[3]);
            mma_bf16(acc[1][0], al1, bh0[0], bh0[1]);
            mma_bf16(acc[1][1], al1, bh0[2], bh0[3]);
            mma_bf16(acc[1][2], al1, bh1[0], bh1[1]);
            mma_bf16(acc[1][3], al1, bh1[2], bh1[3]);
        }
        __syncthreads();
    }

    // epilogue: bn+relu+pool partial
    #pragma unroll
    for (int i = 0; i < 2; i++) {
        int coa = (2 * mw + i) * 16 + g;
        int cob = coa + 8;
        float sca = s_scale[coa], bia = s_bias[coa];
        float scb = s_scale[cob], bib = s_bias[cob];
        float sa = 0.f, sb = 0.f;
        #pragma unroll
        for (int nt = 0; nt < 4; nt++) {
            sa += fmaxf(acc[i][nt][0] * sca + bia, 0.f) + fmaxf(acc[i][nt][1] * sca + bia, 0.f);
            sb += fmaxf(acc[i][nt][2] * scb + bib, 0.f) + fmaxf(acc[i][nt][3] * scb + bib, 0.f);
        }
        sa += __shfl_xor_sync(0xffffffffu, sa, 1);
        sa += __shfl_xor_sync(0xffffffffu, sa, 2);
        sb += __shfl_xor_sync(0xffffffffu, sb, 1);
        sb += __shfl_xor_sync(0xffffffffu, sb, 2);
        if (t4 == 0) {
            g_partial[(size_t)(blk * 2 + nw) * 128 + coa] = sa;
            g_partial[(size_t)(blk * 2 + nw) * 128 + cob] = sb;
        }
    }
}

// ---------------- K4a: stage-1 partial reduction -----------------------------
__global__ void __launch_bounds__(128)
k4a_reduce()
{
    int b = blockIdx.x >> 3, seg = blockIdx.x & 7;
    int co = threadIdx.x;
    const float* pb = g_partial + ((size_t)b * 128 + seg * 16) * 128 + co;
    float s0 = 0.f, s1 = 0.f, s2 = 0.f, s3 = 0.f;
    #pragma unroll
    for (int i = 0; i < 4; i++) {
        s0 += pb[(i * 4 + 0) * 128];
        s1 += pb[(i * 4 + 1) * 128];
        s2 += pb[(i * 4 + 2) * 128];
        s3 += pb[(i * 4 + 3) * 128];
    }
    g_pool_seg[(b * 8 + seg) * 128 + co] = (s0 + s1) + (s2 + s3);
}

// ---------------- K4b: final reduce + fc1 + relu + fc2 -----------------------
__global__ void __launch_bounds__(256)
k4b_fc(const float* __restrict__ fc1w, const float* __restrict__ fc1b,
       const float* __restrict__ fc2w, const float* __restrict__ fc2b,
       float* __restrict__ out)
{
    __shared__ float sp[128];
    __shared__ float hid[256];
    int b = blockIdx.x, tid = threadIdx.x;
    if (tid < 128) {
        const float* ps = g_pool_seg + (size_t)b * 8 * 128 + tid;
        float s = 0.f;
        #pragma unroll
        for (int i = 0; i < 8; i++) s += ps[i * 128];
        sp[tid] = s * (1.f / 4096.f);
    }
    __syncthreads();
    {
        float a = fc1b[tid];
        #pragma unroll 8
        for (int j = 0; j < 128; j++) a += fc1w[tid * 128 + j] * sp[j];
        hid[tid] = fmaxf(a, 0.f);
    }
    __syncthreads();
    if (tid < 200) {
        float a = fc2b[tid];
        #pragma unroll 8
        for (int j = 0; j < 256; j++) a += fc2w[tid * 256 + j] * hid[j];
        out[b * 200 + tid] = a;
    }
}

// ---------------- launch -----------------------------------------------------
extern "C" void kernel_launch(void* const* d_in, const int* in_sizes, int n_in,
                              void* d_out, int out_size)
{
    const float* x    = (const float*)d_in[0];
    const float* o1w  = (const float*)d_in[1];
    const float* o1b  = (const float*)d_in[2];
    const float* c1w  = (const float*)d_in[3];
    const float* c1b  = (const float*)d_in[4];
    const float* g1   = (const float*)d_in[5];
    const float* be1  = (const float*)d_in[6];
    const float* m1   = (const float*)d_in[7];
    const float* v1   = (const float*)d_in[8];
    const float* o2w  = (const float*)d_in[9];
    const float* o2b  = (const float*)d_in[10];
    const float* c2w  = (const float*)d_in[11];
    const float* c2b  = (const float*)d_in[12];
    const float* g2   = (const float*)d_in[13];
    const float* be2  = (const float*)d_in[14];
    const float* m2   = (const float*)d_in[15];
    const float* v2   = (const float*)d_in[16];
    const float* f1w  = (const float*)d_in[17];
    const float* f1b  = (const float*)d_in[18];
    const float* f2w  = (const float*)d_in[19];
    const float* f2b  = (const float*)d_in[20];
    float* out = (float*)d_out;

    cudaFuncSetAttribute(k3_fused, cudaFuncAttributeMaxDynamicSharedMemorySize, K3_SMEM);

    k0_prep<<<441, 256>>>(c2w, o2w, c1w);
    k1_mma<<<2048, 256>>>(x, o1w, o1b, c1b, g1, be1, m1, v1);
    k3_fused<<<2048, 256, K3_SMEM>>>(o2b, c2b, g2, be2, m2, v2);
    k4a_reduce<<<256, 128>>>();
    k4b_fc<<<32, 256>>>(f1w, f1b, f2w, f2b, out);
}

// round 16
// speedup vs baseline: 1.3491x; 1.1666x over previous
#include <cuda_runtime.h>
#include <cuda_bf16.h>
#include <math.h>

#define B_   32
#define HW_  4096
#define C1O  64
#define C2O  128

// ---------------- scratch ----------------------------------------------------
__device__ unsigned short g_h1b[(size_t)B_ * HW_ * C1O];   // channel-last h1 (bf16)
__device__ float g_partial[(size_t)4096 * C2O];            // pooled partials
__device__ float g_pool_seg[256 * C2O];                    // stage-1 reduced partials
#define WF1_N (2 * 8 * 36 * 128)
#define WF2_N (2 * 2 * 36 * 128)
#define WF3_N (2 * 4 * 2 * 128)
__device__ unsigned g_wfrag[WF1_N];                        // conv2 A-frags
__device__ unsigned g_wfrag2[WF2_N];                       // off2 A-frags
__device__ unsigned g_wfrag1[WF3_N];                       // conv1 A-frags

typedef unsigned long long ull;

// ---------------- f32x2 helpers ----------------------------------------------
__device__ __forceinline__ ull fma2(ull a, ull b, ull c) {
    ull d; asm("fma.rn.f32x2 %0, %1, %2, %3;" : "=l"(d) : "l"(a), "l"(b), "l"(c)); return d;
}
__device__ __forceinline__ ull dup2(float v) {
    ull d; unsigned r = __float_as_uint(v);
    asm("mov.b64 %0, {%1, %1};" : "=l"(d) : "r"(r)); return d;
}
__device__ __forceinline__ float2 unpack2(ull v) {
    unsigned lo, hi; asm("mov.b64 {%0, %1}, %2;" : "=r"(lo), "=r"(hi) : "l"(v));
    return make_float2(__uint_as_float(lo), __uint_as_float(hi));
}

// ---------------- mma helpers ------------------------------------------------
__device__ __forceinline__ unsigned smem_u32(const void* p) {
    unsigned a;
    asm("{ .reg .u64 t; cvta.to.shared.u64 t, %1; cvt.u32.u64 %0, t; }" : "=r"(a) : "l"(p));
    return a;
}
__device__ __forceinline__ unsigned pack_bf16(float v0, float v1) {  // low=v0, high=v1
    unsigned d; asm("cvt.rn.bf16x2.f32 %0, %1, %2;" : "=r"(d) : "f"(v1), "f"(v0)); return d;
}
__device__ __forceinline__ unsigned short bf16_1(float v) {
    __nv_bfloat16 b = __float2bfloat16(v);
    return *(unsigned short*)&b;
}
__device__ __forceinline__ float2 ubf2(unsigned u) {      // exact bf16x2 -> f32x2
    return make_float2(__uint_as_float(u << 16), __uint_as_float(u & 0xffff0000u));
}
__device__ __forceinline__ void ldsm4(unsigned& r0, unsigned& r1, unsigned& r2, unsigned& r3,
                                      unsigned addr) {
    asm volatile("ldmatrix.sync.aligned.m8n8.x4.shared.b16 {%0,%1,%2,%3}, [%4];"
                 : "=r"(r0), "=r"(r1), "=r"(r2), "=r"(r3) : "r"(addr));
}
__device__ __forceinline__ void mma_bf16(float* c, const uint4& a, unsigned b0, unsigned b1) {
    asm volatile(
        "mma.sync.aligned.m16n8k16.row.col.f32.bf16.bf16.f32 "
        "{%0,%1,%2,%3}, {%4,%5,%6,%7}, {%8,%9}, {%0,%1,%2,%3};"
        : "+f"(c[0]), "+f"(c[1]), "+f"(c[2]), "+f"(c[3])
        : "r"(a.x), "r"(a.y), "r"(a.z), "r"(a.w), "r"(b0), "r"(b1));
}

// ---------------- K0: build A-fragment weight images -------------------------
__global__ void k0_prep(const float* __restrict__ cw, const float* __restrict__ w2,
                        const float* __restrict__ c1w)
{
    int idx = blockIdx.x * 256 + threadIdx.x;
    if (idx < WF1_N) {
        int r = idx & 3, lane = (idx >> 2) & 31;
        int K = (idx >> 7) % 36;
        int mt = (idx / (128 * 36)) & 7;
        int wt = idx / (128 * 36 * 8);
        int g = lane >> 2, t = lane & 3;
        int co = mt * 16 + g + ((r & 1) ? 8 : 0);
        int kl = 2 * t + ((r & 2) ? 8 : 0);
        float w[2];
        #pragma unroll
        for (int j = 0; j < 2; j++) {
            int e = K * 16 + kl + j;
            int s = e / 192, es = e % 192;
            int tapl = es >> 6, ci = es & 63;
            float wv = cw[co * 576 + ci * 9 + s * 3 + tapl];
            if (wt == 0) w[j] = wv;
            else {
                float hi = __bfloat162float(__float2bfloat16(wv));
                w[j] = wv - hi;
            }
        }
        g_wfrag[idx] = pack_bf16(w[0], w[1]);
    } else if (idx < WF1_N + WF2_N) {
        int i2 = idx - WF1_N;
        int r = i2 & 3, lane = (i2 >> 2) & 31;
        int K = (i2 >> 7) % 36;
        int mt = (i2 / (128 * 36)) & 1;
        int wt = i2 / (128 * 36 * 2);
        int g = lane >> 2, t = lane & 3;
        int co = mt * 16 + g + ((r & 1) ? 8 : 0);
        int kl = 2 * t + ((r & 2) ? 8 : 0);
        float w[2];
        #pragma unroll
        for (int j = 0; j < 2; j++) {
            int e = K * 16 + kl + j;
            int s = e / 192, es = e % 192;
            int tapl = es >> 6, ci = es & 63;
            float wv = (co < 18) ? w2[co * 576 + ci * 9 + s * 3 + tapl] : 0.f;
            if (wt == 0) w[j] = wv;
            else {
                float hi = __bfloat162float(__float2bfloat16(wv));
                w[j] = wv - hi;
            }
        }
        g_wfrag2[i2] = pack_bf16(w[0], w[1]);
    } else if (idx < WF1_N + WF2_N + WF3_N) {
        int i3 = idx - WF1_N - WF2_N;
        int r = i3 & 3, lane = (i3 >> 2) & 31;
        int K = (i3 >> 7) & 1;
        int mt = (i3 / (128 * 2)) & 3;
        int wt = i3 / (128 * 2 * 4);
        int g = lane >> 2, t = lane & 3;
        int co = mt * 16 + g + ((r & 1) ? 8 : 0);
        int kl = 2 * t + ((r & 2) ? 8 : 0);
        float w[2];
        #pragma unroll
        for (int j = 0; j < 2; j++) {
            int e = K * 16 + kl + j;
            float wv = 0.f;
            if (e < 27) {
                int tap = e / 3, ci = e % 3;
                wv = c1w[co * 27 + ci * 9 + tap];
            }
            if (wt == 0) w[j] = wv;
            else {
                float hi = __bfloat162float(__float2bfloat16(wv));
                w[j] = wv - hi;
            }
        }
        g_wfrag1[i3] = pack_bf16(w[0], w[1]);
    }
}

// ---------------- K1: offset1 + deform conv1 + bn1 + relu (mma) --------------
#define VT1_PITCH 80

__global__ void __launch_bounds__(256)
k1_mma(const float* __restrict__ x,
       const float* __restrict__ ow, const float* __restrict__ ob,
       const float* __restrict__ cb, const float* __restrict__ g1,
       const float* __restrict__ be1, const float* __restrict__ m1,
       const float* __restrict__ v1)
{
    __shared__ float s_owT[27 * 20];
    __shared__ float s_ob[18];
    __shared__ float s_off1[18 * 64];
    __shared__ __align__(16) char s_vt[64 * VT1_PITCH];
    __shared__ float s_scale[64], s_bias[64];
    __shared__ float s_out[64 * 65];

    int tid = threadIdx.x;
    int blk = blockIdx.x;
    int h = blk & 63, b = blk >> 6;
    int lane = tid & 31, wid = tid >> 5;

    for (int i = tid; i < 486; i += 256) { int o = i / 27, j = i % 27; s_owT[j * 20 + o] = ow[i]; }
    for (int i = tid; i < 54; i += 256)  { int j = i % 27, o = 18 + i / 27; s_owT[j * 20 + o] = 0.f; }
    if (tid < 18) s_ob[tid] = ob[tid];
    if (tid < 64) {
        float sc = g1[tid] * rsqrtf(v1[tid] + 1e-5f);
        s_scale[tid] = sc;
        s_bias[tid]  = be1[tid] + (cb[tid] - m1[tid]) * sc;
    }
    for (int i = tid; i < (64 * VT1_PITCH) / 16; i += 256)
        ((uint4*)s_vt)[i] = make_uint4(0, 0, 0, 0);
    __syncthreads();

    const float* xb = x + (size_t)b * 3 * 4096;

    // offsets: one loc per thread (tid < 64)
    if (tid < 64) {
        int w = tid;
        float xwin[27];
        #pragma unroll
        for (int ci = 0; ci < 3; ci++)
            #pragma unroll
            for (int kh = 0; kh < 3; kh++)
                #pragma unroll
                for (int kw = 0; kw < 3; kw++) {
                    int yy = h + kh - 1, xx = w + kw - 1;
                    float val = 0.f;
                    if (yy >= 0 && yy < 64 && xx >= 0 && xx < 64)
                        val = xb[ci * 4096 + yy * 64 + xx];
                    xwin[ci * 9 + kh * 3 + kw] = val;
                }
        ull oacc[10];
        #pragma unroll
        for (int p = 0; p < 10; p++) oacc[p] = 0ull;
        #pragma unroll
        for (int j = 0; j < 27; j++) {
            ull vd = dup2(xwin[j]);
            const ulonglong2* wp = (const ulonglong2*)&s_owT[j * 20];
            #pragma unroll
            for (int p = 0; p < 5; p++) {
                ulonglong2 wq = wp[p];
                oacc[p * 2]     = fma2(wq.x, vd, oacc[p * 2]);
                oacc[p * 2 + 1] = fma2(wq.y, vd, oacc[p * 2 + 1]);
            }
        }
        #pragma unroll
        for (int p = 0; p < 9; p++) {
            float2 f = unpack2(oacc[p]);
            s_off1[(2 * p) * 64 + w]     = f.x + s_ob[2 * p];
            s_off1[(2 * p + 1) * 64 + w] = f.y + s_ob[2 * p + 1];
        }
    }
    __syncthreads();

    // cooperative bilinear sampling: 576 tasks (tap, loc), 3 ci each
    for (int u = tid; u < 576; u += 256) {
        int tap = u >> 6, loc = u & 63;
        float dy = s_off1[(tap * 2) * 64 + loc];
        float dx = s_off1[(tap * 2 + 1) * 64 + loc];
        float py = (float)(h + tap / 3 - 1) + dy;
        float px = (float)(loc + tap % 3 - 1) + dx;
        float y0f = floorf(py), x0f = floorf(px);
        int y0 = (int)y0f, x0 = (int)x0f;
        float wy = py - y0f, wx = px - x0f;
        float w00 = (1.f - wy) * (1.f - wx), w01 = (1.f - wy) * wx;
        float w10 = wy * (1.f - wx),         w11 = wy * wx;
        bool vy0 = ((unsigned)y0 < 64u), vy1 = ((unsigned)(y0 + 1) < 64u);
        bool vx0 = ((unsigned)x0 < 64u), vx1 = ((unsigned)(x0 + 1) < 64u);
        bool k00 = vy0 && vx0, k01 = vy0 && vx1, k10 = vy1 && vx0, k11 = vy1 && vx1;
        long long i00 = (long long)y0 * 64 + x0;
        unsigned short* vd = (unsigned short*)(s_vt + loc * VT1_PITCH + (tap * 3) * 2);
        #pragma unroll
        for (int ci = 0; ci < 3; ci++) {
            const float* p = xb + ci * 4096;
            float c00 = k00 ? p[i00]      : 0.f;
            float c01 = k01 ? p[i00 + 1]  : 0.f;
            float c10 = k10 ? p[i00 + 64] : 0.f;
            float c11 = k11 ? p[i00 + 65] : 0.f;
            vd[ci] = bf16_1(c00 * w00 + c01 * w01 + c10 * w10 + c11 * w11);
        }
    }
    __syncthreads();

    // mma: D[64co x 64loc], K=32 (2 ksteps), terms Whi + Wlo (V hi only)
    int mw = wid >> 1, nw = wid & 1;
    int mlm = lane >> 3, rl = lane & 7;
    unsigned smv = smem_u32(s_vt);
    unsigned vb0 = smv + (unsigned)((nw * 32 + (mlm >> 1) * 8 + rl) * VT1_PITCH + (mlm & 1) * 16);
    unsigned vb1 = vb0 + 16 * VT1_PITCH;

    float acc[4][4];
    #pragma unroll
    for (int n = 0; n < 4; n++)
        #pragma unroll
        for (int r = 0; r < 4; r++) acc[n][r] = 0.f;

    const uint4* wf1 = (const uint4*)g_wfrag1;
    #pragma unroll
    for (int k = 0; k < 2; k++) {
        uint4 ah = wf1[((0 * 4 + mw) * 2 + k) * 32 + lane];
        uint4 al = wf1[((1 * 4 + mw) * 2 + k) * 32 + lane];
        unsigned b0[4], b1[4];
        ldsm4(b0[0], b0[1], b0[2], b0[3], vb0 + (unsigned)(k * 32));
        ldsm4(b1[0], b1[1], b1[2], b1[3], vb1 + (unsigned)(k * 32));
        mma_bf16(acc[0], ah, b0[0], b0[1]);
        mma_bf16(acc[1], ah, b0[2], b0[3]);
        mma_bf16(acc[2], ah, b1[0], b1[1]);
        mma_bf16(acc[3], ah, b1[2], b1[3]);
        mma_bf16(acc[0], al, b0[0], b0[1]);
        mma_bf16(acc[1], al, b0[2], b0[3]);
        mma_bf16(acc[2], al, b1[0], b1[1]);
        mma_bf16(acc[3], al, b1[2], b1[3]);
    }

    // epilogue: bn + relu -> s_out -> pack bf16 -> coalesced channel-last store
    int g_ = lane >> 2, t4 = lane & 3;
    int coa = mw * 16 + g_, cob = coa + 8;
    float sca = s_scale[coa], bia = s_bias[coa];
    float scb = s_scale[cob], bib = s_bias[cob];
    #pragma unroll
    for (int nt = 0; nt < 4; nt++) {
        int loc = nw * 32 + nt * 8 + 2 * t4;
        s_out[loc * 65 + coa]       = fmaxf(acc[nt][0] * sca + bia, 0.f);
        s_out[(loc + 1) * 65 + coa] = fmaxf(acc[nt][1] * sca + bia, 0.f);
        s_out[loc * 65 + cob]       = fmaxf(acc[nt][2] * scb + bib, 0.f);
        s_out[(loc + 1) * 65 + cob] = fmaxf(acc[nt][3] * scb + bib, 0.f);
    }
    __syncthreads();

    unsigned* gout = (unsigned*)g_h1b + (size_t)blk * 2048;
    for (int i = tid; i < 2048; i += 256) {
        int loc = i >> 5, cp = i & 31;
        gout[i] = pack_bf16(s_out[loc * 65 + 2 * cp], s_out[loc * 65 + 2 * cp + 1]);
    }
}

// ---------------- K3 (fused): offset2 conv + deform conv2 + bn2 + relu + pool
// h1 consumed in bf16; 2-term W chain, V hi only.
#define VT_PITCH_B 400
#define VT_HI_OFF  0
#define CWYX_OFF   25600
#define CYX_OFF    30208
#define SCALE_OFF  32512
#define BIAS_OFF   33024
#define SOFF_OFF   33536          // float[18*64]
#define K3_SMEM    38144

__global__ void __launch_bounds__(256, 3)
k3_fused(const float* __restrict__ b2, const float* __restrict__ cb,
         const float* __restrict__ g2, const float* __restrict__ be2,
         const float* __restrict__ m2, const float* __restrict__ v2)
{
    extern __shared__ char sm[];
    float2* s_wyx  = (float2*)(sm + CWYX_OFF);
    int*    s_yx   = (int*)(sm + CYX_OFF);
    float*  s_scale = (float*)(sm + SCALE_OFF);
    float*  s_bias  = (float*)(sm + BIAS_OFF);
    float*  s_off   = (float*)(sm + SOFF_OFF);
    unsigned smb = smem_u32(sm);

    int tid = threadIdx.x;
    int blk = blockIdx.x;
    int h = blk & 63, b = blk >> 6;

    if (tid < 128) {
        float sc = g2[tid] * rsqrtf(v2[tid] + 1e-5f);
        s_scale[tid] = sc;
        s_bias[tid]  = be2[tid] + (cb[tid] - m2[tid]) * sc;
    }

    const char* hbB = (const char*)g_h1b + (size_t)b * HW_ * 128;
    int lane = tid & 31, wid = tid >> 5;
    int g = lane >> 2, t4 = lane & 3;
    int mlm = lane >> 3, rl = lane & 7;

    // ===================== Part 1: offsets ====================
    {
        int mt = wid & 1, ng = wid >> 1;
        unsigned vb = smb + (unsigned)((ng * 16 + (mlm >> 1) * 8 + rl) * VT_PITCH_B + (mlm & 1) * 16);

        float acc[2][4];
        #pragma unroll
        for (int n = 0; n < 2; n++)
            #pragma unroll
            for (int r = 0; r < 4; r++) acc[n][r] = 0.f;

        const uint4* wf2 = (const uint4*)g_wfrag2;

        for (int s = 0; s < 3; s++) {
            int y = h + s - 1;
            bool rowv = ((unsigned)y < 64u);

            for (int u = tid; u < 1536; u += 256) {
                int c8 = u & 7, task = u >> 3;
                int tapl = task >> 6, loc = task & 63;
                int x = loc + tapl - 1;
                bool valid = rowv && ((unsigned)x < 64u);
                int ci0 = c8 * 8;
                const uint4* p = (const uint4*)(hbB + ((long long)y * 64 + x) * 128 + ci0 * 2);
                uint4 hv = valid ? *p : make_uint4(0, 0, 0, 0);
                unsigned off = (unsigned)(loc * VT_PITCH_B + (tapl * 64 + ci0) * 2);
                *(uint4*)(sm + VT_HI_OFF + off) = hv;
            }
            __syncthreads();

            int ahb = (mt * 36 + s * 12) * 32 + lane;
            int alb = ahb + 2 * 36 * 32;
            #pragma unroll 1
            for (int k12 = 0; k12 < 12; k12++) {
                uint4 ah = wf2[ahb + k12 * 32];
                unsigned bh[4];
                ldsm4(bh[0], bh[1], bh[2], bh[3], vb + VT_HI_OFF + (unsigned)(k12 * 32));
                mma_bf16(acc[0], ah, bh[0], bh[1]);
                mma_bf16(acc[1], ah, bh[2], bh[3]);
                uint4 al = wf2[alb + k12 * 32];
                mma_bf16(acc[0], al, bh[0], bh[1]);
                mma_bf16(acc[1], al, bh[2], bh[3]);
            }
            __syncthreads();
        }

        #pragma unroll
        for (int nt = 0; nt < 2; nt++) {
            int loc = ng * 16 + nt * 8 + 2 * t4;
            int coa = mt * 16 + g;
            int cob = coa + 8;
            if (coa < 18) {
                float bb = b2[coa];
                s_off[coa * 64 + loc]     = acc[nt][0] + bb;
                s_off[coa * 64 + loc + 1] = acc[nt][1] + bb;
            }
            if (cob < 18) {
                float bb = b2[cob];
                s_off[cob * 64 + loc]     = acc[nt][2] + bb;
                s_off[cob * 64 + loc + 1] = acc[nt][3] + bb;
            }
        }
    }
    __syncthreads();

    // ===================== Part 2: deform conv2 ==============================
    for (int t = tid; t < 576; t += 256) {
        int tap = t >> 6, loc = t & 63;
        float dy = s_off[(tap * 2) * 64 + loc];
        float dx = s_off[(tap * 2 + 1) * 64 + loc];
        float py = (float)(h + tap / 3 - 1) + dy;
        float px = (float)(loc + tap % 3 - 1) + dx;
        float y0f = floorf(py), x0f = floorf(px);
        int y0 = (int)y0f, x0 = (int)x0f;
        s_yx[t] = (y0 << 16) | (x0 & 0xffff);
        s_wyx[t] = make_float2(py - y0f, px - x0f);
    }
    __syncthreads();

    int mw = wid >> 1, nw = wid & 1;
    unsigned vb0 = smb + (unsigned)((nw * 32 + (mlm >> 1) * 8 + rl) * VT_PITCH_B + (mlm & 1) * 16);
    unsigned vb1 = vb0 + 16 * VT_PITCH_B;

    float acc[2][4][4];
    #pragma unroll
    for (int i = 0; i < 2; i++)
        #pragma unroll
        for (int n = 0; n < 4; n++)
            #pragma unroll
            for (int r = 0; r < 4; r++) acc[i][n][r] = 0.f;

    const uint4* wf = (const uint4*)g_wfrag;

    for (int s = 0; s < 3; s++) {
        // phase B: bilinear sampling from bf16 h1 (4 corner uint4 loads / chunk)
        for (int u = tid; u < 1536; u += 256) {
            int c8 = u & 7, task = u >> 3;
            int tapl = task >> 6, loc = task & 63;
            int t = (s * 3 + tapl) * 64 + loc;
            int yx = s_yx[t];
            int y0 = yx >> 16, x0 = (short)(yx & 0xffff);
            float2 wyx = s_wyx[t];
            float wy = wyx.x, wx = wyx.y;
            float w00 = (1.f - wy) * (1.f - wx), w01 = (1.f - wy) * wx;
            float w10 = wy * (1.f - wx),          w11 = wy * wx;
            bool vy0 = ((unsigned)y0 < 64u), vy1 = ((unsigned)(y0 + 1) < 64u);
            bool vx0 = ((unsigned)x0 < 64u), vx1 = ((unsigned)(x0 + 1) < 64u);
            int ci0 = c8 * 8;
            const char* p00 = hbB + ((long long)y0 * 64 + x0) * 128 + ci0 * 2;
            uint4 z = make_uint4(0, 0, 0, 0);
            bool k00 = vy0 && vx0, k01 = vy0 && vx1, k10 = vy1 && vx0, k11 = vy1 && vx1;
            uint4 c00 = k00 ? *(const uint4*)(p00)          : z;
            uint4 c01 = k01 ? *(const uint4*)(p00 + 128)    : z;
            uint4 c10 = k10 ? *(const uint4*)(p00 + 8192)   : z;
            uint4 c11 = k11 ? *(const uint4*)(p00 + 8320)   : z;

            uint4 hi4;
            {
                float2 a0 = ubf2(c00.x), a1 = ubf2(c01.x), a2 = ubf2(c10.x), a3 = ubf2(c11.x);
                hi4.x = pack_bf16(a0.x * w00 + a1.x * w01 + a2.x * w10 + a3.x * w11,
                                  a0.y * w00 + a1.y * w01 + a2.y * w10 + a3.y * w11);
            }
            {
                float2 a0 = ubf2(c00.y), a1 = ubf2(c01.y), a2 = ubf2(c10.y), a3 = ubf2(c11.y);
                hi4.y = pack_bf16(a0.x * w00 + a1.x * w01 + a2.x * w10 + a3.x * w11,
                                  a0.y * w00 + a1.y * w01 + a2.y * w10 + a3.y * w11);
            }
            {
                float2 a0 = ubf2(c00.z), a1 = ubf2(c01.z), a2 = ubf2(c10.z), a3 = ubf2(c11.z);
                hi4.z = pack_bf16(a0.x * w00 + a1.x * w01 + a2.x * w10 + a3.x * w11,
                                  a0.y * w00 + a1.y * w01 + a2.y * w10 + a3.y * w11);
            }
            {
                float2 a0 = ubf2(c00.w), a1 = ubf2(c01.w), a2 = ubf2(c10.w), a3 = ubf2(c11.w);
                hi4.w = pack_bf16(a0.x * w00 + a1.x * w01 + a2.x * w10 + a3.x * w11,
                                  a0.y * w00 + a1.y * w01 + a2.y * w10 + a3.y * w11);
            }
            unsigned off = (unsigned)(loc * VT_PITCH_B + (tapl * 64 + ci0) * 2);
            *(uint4*)(sm + VT_HI_OFF + off) = hi4;
        }
        __syncthreads();

        int ahb0 = ((2 * mw) * 36 + s * 12) * 32 + lane;
        int ahb1 = ahb0 + 36 * 32;
        int alb0 = ahb0 + 288 * 32;
        int alb1 = alb0 + 36 * 32;
        #pragma unroll 1
        for (int k12 = 0; k12 < 12; k12++) {
            uint4 ah0 = wf[ahb0 + k12 * 32];
            uint4 ah1 = wf[ahb1 + k12 * 32];
            unsigned bh0[4], bh1[4];
            ldsm4(bh0[0], bh0[1], bh0[2], bh0[3], vb0 + VT_HI_OFF + (unsigned)(k12 * 32));
            ldsm4(bh1[0], bh1[1], bh1[2], bh1[3], vb1 + VT_HI_OFF + (unsigned)(k12 * 32));
            mma_bf16(acc[0][0], ah0, bh0[0], bh0[1]);
            mma_bf16(acc[0][1], ah0, bh0[2], bh0[3]);
            mma_bf16(acc[0][2], ah0, bh1[0], bh1[1]);
            mma_bf16(acc[0][3], ah0, bh1[2], bh1[3]);
            mma_bf16(acc[1][0], ah1, bh0[0], bh0[1]);
            mma_bf16(acc[1][1], ah1, bh0[2], bh0[3]);
            mma_bf16(acc[1][2], ah1, bh1[0], bh1[1]);
            mma_bf16(acc[1][3], ah1, bh1[2], bh1[3]);
            uint4 al0 = wf[alb0 + k12 * 32];
            uint4 al1 = wf[alb1 + k12 * 32];
            mma_bf16(acc[0][0], al0, bh0[0], bh0[1]);
            mma_bf16(acc[0][1], al0, bh0[2], bh0[3]);
            mma_bf16(acc[0][2], al0, bh1[0], bh1[1]);
            mma_bf16(acc[0][3], al0, bh1[2], bh1[3]);
            mma_bf16(acc[1][0], al1, bh0[0], bh0[1]);
            mma_bf16(acc[1][1], al1, bh0[2], bh0[3]);
            mma_bf16(acc[1][2], al1, bh1[0], bh1[1]);
            mma_bf16(acc[1][3], al1, bh1[2], bh1[3]);
        }
        __syncthreads();
    }

    // epilogue: bn+relu+pool partial
    #pragma unroll
    for (int i = 0; i < 2; i++) {
        int coa = (2 * mw + i) * 16 + g;
        int cob = coa + 8;
        float sca = s_scale[coa], bia = s_bias[coa];
        float scb = s_scale[cob], bib = s_bias[cob];
        float sa = 0.f, sb = 0.f;
        #pragma unroll
        for (int nt = 0; nt < 4; nt++) {
            sa += fmaxf(acc[i][nt][0] * sca + bia, 0.f) + fmaxf(acc[i][nt][1] * sca + bia, 0.f);
            sb += fmaxf(acc[i][nt][2] * scb + bib, 0.f) + fmaxf(acc[i][nt][3] * scb + bib, 0.f);
        }
        sa += __shfl_xor_sync(0xffffffffu, sa, 1);
        sa += __shfl_xor_sync(0xffffffffu, sa, 2);
        sb += __shfl_xor_sync(0xffffffffu, sb, 1);
        sb += __shfl_xor_sync(0xffffffffu, sb, 2);
        if (t4 == 0) {
            g_partial[(size_t)(blk * 2 + nw) * 128 + coa] = sa;
            g_partial[(size_t)(blk * 2 + nw) * 128 + cob] = sb;
        }
    }
}

// ---------------- K4a: stage-1 partial reduction -----------------------------
__global__ void __launch_bounds__(128)
k4a_reduce()
{
    int b = blockIdx.x >> 3, seg = blockIdx.x & 7;
    int co = threadIdx.x;
    const float* pb = g_partial + ((size_t)b * 128 + seg * 16) * 128 + co;
    float s0 = 0.f, s1 = 0.f, s2 = 0.f, s3 = 0.f;
    #pragma unroll
    for (int i = 0; i < 4; i++) {
        s0 += pb[(i * 4 + 0) * 128];
        s1 += pb[(i * 4 + 1) * 128];
        s2 += pb[(i * 4 + 2) * 128];
        s3 += pb[(i * 4 + 3) * 128];
    }
    g_pool_seg[(b * 8 + seg) * 128 + co] = (s0 + s1) + (s2 + s3);
}

// ---------------- K4b: final reduce + fc1 + relu + fc2 -----------------------
__global__ void __launch_bounds__(256)
k4b_fc(const float* __restrict__ fc1w, const float* __restrict__ fc1b,
       const float* __restrict__ fc2w, const float* __restrict__ fc2b,
       float* __restrict__ out)
{
    __shared__ float sp[128];
    __shared__ float hid[256];
    int b = blockIdx.x, tid = threadIdx.x;
    if (tid < 128) {
        const float* ps = g_pool_seg + (size_t)b * 8 * 128 + tid;
        float s = 0.f;
        #pragma unroll
        for (int i = 0; i < 8; i++) s += ps[i * 128];
        sp[tid] = s * (1.f / 4096.f);
    }
    __syncthreads();
    {
        float a = fc1b[tid];
        #pragma unroll 8
        for (int j = 0; j < 128; j++) a += fc1w[tid * 128 + j] * sp[j];
        hid[tid] = fmaxf(a, 0.f);
    }
    __syncthreads();
    if (tid < 200) {
        float a = fc2b[tid];
        #pragma unroll 8
        for (int j = 0; j < 256; j++) a += fc2w[tid * 256 + j] * hid[j];
        out[b * 200 + tid] = a;
    }
}

// ---------------- launch -----------------------------------------------------
extern "C" void kernel_launch(void* const* d_in, const int* in_sizes, int n_in,
                              void* d_out, int out_size)
{
    const float* x    = (const float*)d_in[0];
    const float* o1w  = (const float*)d_in[1];
    const float* o1b  = (const float*)d_in[2];
    const float* c1w  = (const float*)d_in[3];
    const float* c1b  = (const float*)d_in[4];
    const float* g1   = (const float*)d_in[5];
    const float* be1  = (const float*)d_in[6];
    const float* m1   = (const float*)d_in[7];
    const float* v1   = (const float*)d_in[8];
    const float* o2w  = (const float*)d_in[9];
    const float* o2b  = (const float*)d_in[10];
    const float* c2w  = (const float*)d_in[11];
    const float* c2b  = (const float*)d_in[12];
    const float* g2   = (const float*)d_in[13];
    const float* be2  = (const float*)d_in[14];
    const float* m2   = (const float*)d_in[15];
    const float* v2   = (const float*)d_in[16];
    const float* f1w  = (const float*)d_in[17];
    const float* f1b  = (const float*)d_in[18];
    const float* f2w  = (const float*)d_in[19];
    const float* f2b  = (const float*)d_in[20];
    float* out = (float*)d_out;

    cudaFuncSetAttribute(k3_fused, cudaFuncAttributeMaxDynamicSharedMemorySize, K3_SMEM);

    k0_prep<<<441, 256>>>(c2w, o2w, c1w);
    k1_mma<<<2048, 256>>>(x, o1w, o1b, c1b, g1, be1, m1, v1);
    k3_fused<<<2048, 256, K3_SMEM>>>(o2b, c2b, g2, be2, m2, v2);
    k4a_reduce<<<256, 128>>>();
    k4b_fc<<<32, 256>>>(f1w, f1b, f2w, f2b, out);
}

// round 17
// speedup vs baseline: 1.5030x; 1.1140x over previous
#include <cuda_runtime.h>
#include <cuda_fp16.h>
#include <math.h>

#define B_   32
#define HW_  4096
#define C1O  64
#define C2O  128

// ---------------- scratch ----------------------------------------------------
__device__ unsigned short g_h1b[(size_t)B_ * HW_ * C1O];   // channel-last h1 (fp16)
__device__ float g_partial[(size_t)4096 * C2O];            // pooled partials
__device__ float g_pool_seg[256 * C2O];                    // stage-1 reduced partials
#define WF1_N (8 * 36 * 128)
#define WF2_N (2 * 36 * 128)
#define WF3_N (4 * 2 * 128)
__device__ unsigned g_wfrag[WF1_N];                        // conv2 A-frags (fp16)
__device__ unsigned g_wfrag2[WF2_N];                       // off2 A-frags
__device__ unsigned g_wfrag1[WF3_N];                       // conv1 A-frags

typedef unsigned long long ull;

// ---------------- f32x2 helpers ----------------------------------------------
__device__ __forceinline__ ull fma2(ull a, ull b, ull c) {
    ull d; asm("fma.rn.f32x2 %0, %1, %2, %3;" : "=l"(d) : "l"(a), "l"(b), "l"(c)); return d;
}
__device__ __forceinline__ ull dup2(float v) {
    ull d; unsigned r = __float_as_uint(v);
    asm("mov.b64 %0, {%1, %1};" : "=l"(d) : "r"(r)); return d;
}
__device__ __forceinline__ float2 unpack2(ull v) {
    unsigned lo, hi; asm("mov.b64 {%0, %1}, %2;" : "=r"(lo), "=r"(hi) : "l"(v));
    return make_float2(__uint_as_float(lo), __uint_as_float(hi));
}

// ---------------- mma helpers (fp16) -----------------------------------------
__device__ __forceinline__ unsigned smem_u32(const void* p) {
    unsigned a;
    asm("{ .reg .u64 t; cvta.to.shared.u64 t, %1; cvt.u32.u64 %0, t; }" : "=r"(a) : "l"(p));
    return a;
}
__device__ __forceinline__ unsigned pack_f16(float v0, float v1) {  // low=v0, high=v1
    unsigned d; asm("cvt.rn.f16x2.f32 %0, %1, %2;" : "=r"(d) : "f"(v1), "f"(v0)); return d;
}
__device__ __forceinline__ unsigned short f16_1(float v) {
    __half h = __float2half_rn(v);
    return *(unsigned short*)&h;
}
__device__ __forceinline__ float2 uhf2(unsigned u) {      // fp16x2 -> f32x2 (exact)
    __half2 h = *(__half2*)&u;
    return __half22float2(h);
}
__device__ __forceinline__ void ldsm4(unsigned& r0, unsigned& r1, unsigned& r2, unsigned& r3,
                                      unsigned addr) {
    asm volatile("ldmatrix.sync.aligned.m8n8.x4.shared.b16 {%0,%1,%2,%3}, [%4];"
                 : "=r"(r0), "=r"(r1), "=r"(r2), "=r"(r3) : "r"(addr));
}
__device__ __forceinline__ void mma_f16(float* c, const uint4& a, unsigned b0, unsigned b1) {
    asm volatile(
        "mma.sync.aligned.m16n8k16.row.col.f32.f16.f16.f32 "
        "{%0,%1,%2,%3}, {%4,%5,%6,%7}, {%8,%9}, {%0,%1,%2,%3};"
        : "+f"(c[0]), "+f"(c[1]), "+f"(c[2]), "+f"(c[3])
        : "r"(a.x), "r"(a.y), "r"(a.z), "r"(a.w), "r"(b0), "r"(b1));
}

// ---------------- K0: build A-fragment weight images (fp16, single term) -----
__global__ void k0_prep(const float* __restrict__ cw, const float* __restrict__ w2,
                        const float* __restrict__ c1w)
{
    int idx = blockIdx.x * 256 + threadIdx.x;
    if (idx < WF1_N) {
        int r = idx & 3, lane = (idx >> 2) & 31;
        int K = (idx >> 7) % 36;
        int mt = (idx / (128 * 36)) & 7;
        int g = lane >> 2, t = lane & 3;
        int co = mt * 16 + g + ((r & 1) ? 8 : 0);
        int kl = 2 * t + ((r & 2) ? 8 : 0);
        float w[2];
        #pragma unroll
        for (int j = 0; j < 2; j++) {
            int e = K * 16 + kl + j;
            int s = e / 192, es = e % 192;
            int tapl = es >> 6, ci = es & 63;
            w[j] = cw[co * 576 + ci * 9 + s * 3 + tapl];
        }
        g_wfrag[idx] = pack_f16(w[0], w[1]);
    } else if (idx < WF1_N + WF2_N) {
        int i2 = idx - WF1_N;
        int r = i2 & 3, lane = (i2 >> 2) & 31;
        int K = (i2 >> 7) % 36;
        int mt = (i2 / (128 * 36)) & 1;
        int g = lane >> 2, t = lane & 3;
        int co = mt * 16 + g + ((r & 1) ? 8 : 0);
        int kl = 2 * t + ((r & 2) ? 8 : 0);
        float w[2];
        #pragma unroll
        for (int j = 0; j < 2; j++) {
            int e = K * 16 + kl + j;
            int s = e / 192, es = e % 192;
            int tapl = es >> 6, ci = es & 63;
            w[j] = (co < 18) ? w2[co * 576 + ci * 9 + s * 3 + tapl] : 0.f;
        }
        g_wfrag2[i2] = pack_f16(w[0], w[1]);
    } else if (idx < WF1_N + WF2_N + WF3_N) {
        int i3 = idx - WF1_N - WF2_N;
        int r = i3 & 3, lane = (i3 >> 2) & 31;
        int K = (i3 >> 7) & 1;
        int mt = (i3 / (128 * 2)) & 3;
        int g = lane >> 2, t = lane & 3;
        int co = mt * 16 + g + ((r & 1) ? 8 : 0);
        int kl = 2 * t + ((r & 2) ? 8 : 0);
        float w[2];
        #pragma unroll
        for (int j = 0; j < 2; j++) {
            int e = K * 16 + kl + j;
            float wv = 0.f;
            if (e < 27) {
                int tap = e / 3, ci = e % 3;
                wv = c1w[co * 27 + ci * 9 + tap];
            }
            w[j] = wv;
        }
        g_wfrag1[i3] = pack_f16(w[0], w[1]);
    }
}

// ---------------- K1: offset1 + deform conv1 + bn1 + relu (fp16 mma) ---------
#define VT1_PITCH 80

__global__ void __launch_bounds__(256)
k1_mma(const float* __restrict__ x,
       const float* __restrict__ ow, const float* __restrict__ ob,
       const float* __restrict__ cb, const float* __restrict__ g1,
       const float* __restrict__ be1, const float* __restrict__ m1,
       const float* __restrict__ v1)
{
    __shared__ float s_owT[27 * 20];
    __shared__ float s_ob[18];
    __shared__ float s_off1[18 * 64];
    __shared__ __align__(16) char s_vt[64 * VT1_PITCH];
    __shared__ float s_scale[64], s_bias[64];
    __shared__ float s_out[64 * 65];

    int tid = threadIdx.x;
    int blk = blockIdx.x;
    int h = blk & 63, b = blk >> 6;
    int lane = tid & 31, wid = tid >> 5;

    for (int i = tid; i < 486; i += 256) { int o = i / 27, j = i % 27; s_owT[j * 20 + o] = ow[i]; }
    for (int i = tid; i < 54; i += 256)  { int j = i % 27, o = 18 + i / 27; s_owT[j * 20 + o] = 0.f; }
    if (tid < 18) s_ob[tid] = ob[tid];
    if (tid < 64) {
        float sc = g1[tid] * rsqrtf(v1[tid] + 1e-5f);
        s_scale[tid] = sc;
        s_bias[tid]  = be1[tid] + (cb[tid] - m1[tid]) * sc;
    }
    for (int i = tid; i < (64 * VT1_PITCH) / 16; i += 256)
        ((uint4*)s_vt)[i] = make_uint4(0, 0, 0, 0);
    __syncthreads();

    const float* xb = x + (size_t)b * 3 * 4096;

    // offsets: one loc per thread (tid < 64)
    if (tid < 64) {
        int w = tid;
        float xwin[27];
        #pragma unroll
        for (int ci = 0; ci < 3; ci++)
            #pragma unroll
            for (int kh = 0; kh < 3; kh++)
                #pragma unroll
                for (int kw = 0; kw < 3; kw++) {
                    int yy = h + kh - 1, xx = w + kw - 1;
                    float val = 0.f;
                    if (yy >= 0 && yy < 64 && xx >= 0 && xx < 64)
                        val = xb[ci * 4096 + yy * 64 + xx];
                    xwin[ci * 9 + kh * 3 + kw] = val;
                }
        ull oacc[10];
        #pragma unroll
        for (int p = 0; p < 10; p++) oacc[p] = 0ull;
        #pragma unroll
        for (int j = 0; j < 27; j++) {
            ull vd = dup2(xwin[j]);
            const ulonglong2* wp = (const ulonglong2*)&s_owT[j * 20];
            #pragma unroll
            for (int p = 0; p < 5; p++) {
                ulonglong2 wq = wp[p];
                oacc[p * 2]     = fma2(wq.x, vd, oacc[p * 2]);
                oacc[p * 2 + 1] = fma2(wq.y, vd, oacc[p * 2 + 1]);
            }
        }
        #pragma unroll
        for (int p = 0; p < 9; p++) {
            float2 f = unpack2(oacc[p]);
            s_off1[(2 * p) * 64 + w]     = f.x + s_ob[2 * p];
            s_off1[(2 * p + 1) * 64 + w] = f.y + s_ob[2 * p + 1];
        }
    }
    __syncthreads();

    // cooperative bilinear sampling: 576 tasks (tap, loc), 3 ci each
    for (int u = tid; u < 576; u += 256) {
        int tap = u >> 6, loc = u & 63;
        float dy = s_off1[(tap * 2) * 64 + loc];
        float dx = s_off1[(tap * 2 + 1) * 64 + loc];
        float py = (float)(h + tap / 3 - 1) + dy;
        float px = (float)(loc + tap % 3 - 1) + dx;
        float y0f = floorf(py), x0f = floorf(px);
        int y0 = (int)y0f, x0 = (int)x0f;
        float wy = py - y0f, wx = px - x0f;
        float w00 = (1.f - wy) * (1.f - wx), w01 = (1.f - wy) * wx;
        float w10 = wy * (1.f - wx),         w11 = wy * wx;
        bool vy0 = ((unsigned)y0 < 64u), vy1 = ((unsigned)(y0 + 1) < 64u);
        bool vx0 = ((unsigned)x0 < 64u), vx1 = ((unsigned)(x0 + 1) < 64u);
        bool k00 = vy0 && vx0, k01 = vy0 && vx1, k10 = vy1 && vx0, k11 = vy1 && vx1;
        long long i00 = (long long)y0 * 64 + x0;
        unsigned short* vd = (unsigned short*)(s_vt + loc * VT1_PITCH + (tap * 3) * 2);
        #pragma unroll
        for (int ci = 0; ci < 3; ci++) {
            const float* p = xb + ci * 4096;
            float c00 = k00 ? p[i00]      : 0.f;
            float c01 = k01 ? p[i00 + 1]  : 0.f;
            float c10 = k10 ? p[i00 + 64] : 0.f;
            float c11 = k11 ? p[i00 + 65] : 0.f;
            vd[ci] = f16_1(c00 * w00 + c01 * w01 + c10 * w10 + c11 * w11);
        }
    }
    __syncthreads();

    // mma: D[64co x 64loc], K=32 (2 ksteps), single fp16 term
    int mw = wid >> 1, nw = wid & 1;
    int mlm = lane >> 3, rl = lane & 7;
    unsigned smv = smem_u32(s_vt);
    unsigned vb0 = smv + (unsigned)((nw * 32 + (mlm >> 1) * 8 + rl) * VT1_PITCH + (mlm & 1) * 16);
    unsigned vb1 = vb0 + 16 * VT1_PITCH;

    float acc[4][4];
    #pragma unroll
    for (int n = 0; n < 4; n++)
        #pragma unroll
        for (int r = 0; r < 4; r++) acc[n][r] = 0.f;

    const uint4* wf1 = (const uint4*)g_wfrag1;
    #pragma unroll
    for (int k = 0; k < 2; k++) {
        uint4 ah = wf1[(mw * 2 + k) * 32 + lane];
        unsigned b0[4], b1[4];
        ldsm4(b0[0], b0[1], b0[2], b0[3], vb0 + (unsigned)(k * 32));
        ldsm4(b1[0], b1[1], b1[2], b1[3], vb1 + (unsigned)(k * 32));
        mma_f16(acc[0], ah, b0[0], b0[1]);
        mma_f16(acc[1], ah, b0[2], b0[3]);
        mma_f16(acc[2], ah, b1[0], b1[1]);
        mma_f16(acc[3], ah, b1[2], b1[3]);
    }

    // epilogue: bn + relu -> s_out -> pack fp16 -> coalesced channel-last store
    int g_ = lane >> 2, t4 = lane & 3;
    int coa = mw * 16 + g_, cob = coa + 8;
    float sca = s_scale[coa], bia = s_bias[coa];
    float scb = s_scale[cob], bib = s_bias[cob];
    #pragma unroll
    for (int nt = 0; nt < 4; nt++) {
        int loc = nw * 32 + nt * 8 + 2 * t4;
        s_out[loc * 65 + coa]       = fmaxf(acc[nt][0] * sca + bia, 0.f);
        s_out[(loc + 1) * 65 + coa] = fmaxf(acc[nt][1] * sca + bia, 0.f);
        s_out[loc * 65 + cob]       = fmaxf(acc[nt][2] * scb + bib, 0.f);
        s_out[(loc + 1) * 65 + cob] = fmaxf(acc[nt][3] * scb + bib, 0.f);
    }
    __syncthreads();

    unsigned* gout = (unsigned*)g_h1b + (size_t)blk * 2048;
    for (int i = tid; i < 2048; i += 256) {
        int loc = i >> 5, cp = i & 31;
        gout[i] = pack_f16(s_out[loc * 65 + 2 * cp], s_out[loc * 65 + 2 * cp + 1]);
    }
}

// ---------------- K3 (fused): offset2 conv + deform conv2 + bn2 + relu + pool
// h1 consumed in fp16; single-term fp16 W.
#define VT_PITCH_B 400
#define VT_HI_OFF  0
#define CWYX_OFF   25600
#define CYX_OFF    30208
#define SCALE_OFF  32512
#define BIAS_OFF   33024
#define SOFF_OFF   33536          // float[18*64]
#define K3_SMEM    38144

__global__ void __launch_bounds__(256, 3)
k3_fused(const float* __restrict__ b2, const float* __restrict__ cb,
         const float* __restrict__ g2, const float* __restrict__ be2,
         const float* __restrict__ m2, const float* __restrict__ v2)
{
    extern __shared__ char sm[];
    float2* s_wyx  = (float2*)(sm + CWYX_OFF);
    int*    s_yx   = (int*)(sm + CYX_OFF);
    float*  s_scale = (float*)(sm + SCALE_OFF);
    float*  s_bias  = (float*)(sm + BIAS_OFF);
    float*  s_off   = (float*)(sm + SOFF_OFF);
    unsigned smb = smem_u32(sm);

    int tid = threadIdx.x;
    int blk = blockIdx.x;
    int h = blk & 63, b = blk >> 6;

    if (tid < 128) {
        float sc = g2[tid] * rsqrtf(v2[tid] + 1e-5f);
        s_scale[tid] = sc;
        s_bias[tid]  = be2[tid] + (cb[tid] - m2[tid]) * sc;
    }

    const char* hbB = (const char*)g_h1b + (size_t)b * HW_ * 128;
    int lane = tid & 31, wid = tid >> 5;
    int g = lane >> 2, t4 = lane & 3;
    int mlm = lane >> 3, rl = lane & 7;

    // ===================== Part 1: offsets ====================
    {
        int mt = wid & 1, ng = wid >> 1;
        unsigned vb = smb + (unsigned)((ng * 16 + (mlm >> 1) * 8 + rl) * VT_PITCH_B + (mlm & 1) * 16);

        float acc[2][4];
        #pragma unroll
        for (int n = 0; n < 2; n++)
            #pragma unroll
            for (int r = 0; r < 4; r++) acc[n][r] = 0.f;

        const uint4* wf2 = (const uint4*)g_wfrag2;

        for (int s = 0; s < 3; s++) {
            int y = h + s - 1;
            bool rowv = ((unsigned)y < 64u);

            for (int u = tid; u < 1536; u += 256) {
                int c8 = u & 7, task = u >> 3;
                int tapl = task >> 6, loc = task & 63;
                int x = loc + tapl - 1;
                bool valid = rowv && ((unsigned)x < 64u);
                int ci0 = c8 * 8;
                const uint4* p = (const uint4*)(hbB + ((long long)y * 64 + x) * 128 + ci0 * 2);
                uint4 hv = valid ? *p : make_uint4(0, 0, 0, 0);
                unsigned off = (unsigned)(loc * VT_PITCH_B + (tapl * 64 + ci0) * 2);
                *(uint4*)(sm + VT_HI_OFF + off) = hv;
            }
            __syncthreads();

            int ahb = (mt * 36 + s * 12) * 32 + lane;
            #pragma unroll 1
            for (int k12 = 0; k12 < 12; k12++) {
                uint4 ah = wf2[ahb + k12 * 32];
                unsigned bh[4];
                ldsm4(bh[0], bh[1], bh[2], bh[3], vb + VT_HI_OFF + (unsigned)(k12 * 32));
                mma_f16(acc[0], ah, bh[0], bh[1]);
                mma_f16(acc[1], ah, bh[2], bh[3]);
            }
            __syncthreads();
        }

        #pragma unroll
        for (int nt = 0; nt < 2; nt++) {
            int loc = ng * 16 + nt * 8 + 2 * t4;
            int coa = mt * 16 + g;
            int cob = coa + 8;
            if (coa < 18) {
                float bb = b2[coa];
                s_off[coa * 64 + loc]     = acc[nt][0] + bb;
                s_off[coa * 64 + loc + 1] = acc[nt][1] + bb;
            }
            if (cob < 18) {
                float bb = b2[cob];
                s_off[cob * 64 + loc]     = acc[nt][2] + bb;
                s_off[cob * 64 + loc + 1] = acc[nt][3] + bb;
            }
        }
    }
    __syncthreads();

    // ===================== Part 2: deform conv2 ==============================
    for (int t = tid; t < 576; t += 256) {
        int tap = t >> 6, loc = t & 63;
        float dy = s_off[(tap * 2) * 64 + loc];
        float dx = s_off[(tap * 2 + 1) * 64 + loc];
        float py = (float)(h + tap / 3 - 1) + dy;
        float px = (float)(loc + tap % 3 - 1) + dx;
        float y0f = floorf(py), x0f = floorf(px);
        int y0 = (int)y0f, x0 = (int)x0f;
        s_yx[t] = (y0 << 16) | (x0 & 0xffff);
        s_wyx[t] = make_float2(py - y0f, px - x0f);
    }
    __syncthreads();

    int mw = wid >> 1, nw = wid & 1;
    unsigned vb0 = smb + (unsigned)((nw * 32 + (mlm >> 1) * 8 + rl) * VT_PITCH_B + (mlm & 1) * 16);
    unsigned vb1 = vb0 + 16 * VT_PITCH_B;

    float acc[2][4][4];
    #pragma unroll
    for (int i = 0; i < 2; i++)
        #pragma unroll
        for (int n = 0; n < 4; n++)
            #pragma unroll
            for (int r = 0; r < 4; r++) acc[i][n][r] = 0.f;

    const uint4* wf = (const uint4*)g_wfrag;

    for (int s = 0; s < 3; s++) {
        // phase B: bilinear sampling from fp16 h1 (4 corner uint4 loads / chunk)
        for (int u = tid; u < 1536; u += 256) {
            int c8 = u & 7, task = u >> 3;
            int tapl = task >> 6, loc = task & 63;
            int t = (s * 3 + tapl) * 64 + loc;
            int yx = s_yx[t];
            int y0 = yx >> 16, x0 = (short)(yx & 0xffff);
            float2 wyx = s_wyx[t];
            float wy = wyx.x, wx = wyx.y;
            float w00 = (1.f - wy) * (1.f - wx), w01 = (1.f - wy) * wx;
            float w10 = wy * (1.f - wx),          w11 = wy * wx;
            bool vy0 = ((unsigned)y0 < 64u), vy1 = ((unsigned)(y0 + 1) < 64u);
            bool vx0 = ((unsigned)x0 < 64u), vx1 = ((unsigned)(x0 + 1) < 64u);
            int ci0 = c8 * 8;
            const char* p00 = hbB + ((long long)y0 * 64 + x0) * 128 + ci0 * 2;
            uint4 z = make_uint4(0, 0, 0, 0);
            bool k00 = vy0 && vx0, k01 = vy0 && vx1, k10 = vy1 && vx0, k11 = vy1 && vx1;
            uint4 c00 = k00 ? *(const uint4*)(p00)          : z;
            uint4 c01 = k01 ? *(const uint4*)(p00 + 128)    : z;
            uint4 c10 = k10 ? *(const uint4*)(p00 + 8192)   : z;
            uint4 c11 = k11 ? *(const uint4*)(p00 + 8320)   : z;

            uint4 hi4;
            {
                float2 a0 = uhf2(c00.x), a1 = uhf2(c01.x), a2 = uhf2(c10.x), a3 = uhf2(c11.x);
                hi4.x = pack_f16(a0.x * w00 + a1.x * w01 + a2.x * w10 + a3.x * w11,
                                 a0.y * w00 + a1.y * w01 + a2.y * w10 + a3.y * w11);
            }
            {
                float2 a0 = uhf2(c00.y), a1 = uhf2(c01.y), a2 = uhf2(c10.y), a3 = uhf2(c11.y);
                hi4.y = pack_f16(a0.x * w00 + a1.x * w01 + a2.x * w10 + a3.x * w11,
                                 a0.y * w00 + a1.y * w01 + a2.y * w10 + a3.y * w11);
            }
            {
                float2 a0 = uhf2(c00.z), a1 = uhf2(c01.z), a2 = uhf2(c10.z), a3 = uhf2(c11.z);
                hi4.z = pack_f16(a0.x * w00 + a1.x * w01 + a2.x * w10 + a3.x * w11,
                                 a0.y * w00 + a1.y * w01 + a2.y * w10 + a3.y * w11);
            }
            {
                float2 a0 = uhf2(c00.w), a1 = uhf2(c01.w), a2 = uhf2(c10.w), a3 = uhf2(c11.w);
                hi4.w = pack_f16(a0.x * w00 + a1.x * w01 + a2.x * w10 + a3.x * w11,
                                 a0.y * w00 + a1.y * w01 + a2.y * w10 + a3.y * w11);
            }
            unsigned off = (unsigned)(loc * VT_PITCH_B + (tapl * 64 + ci0) * 2);
            *(uint4*)(sm + VT_HI_OFF + off) = hi4;
        }
        __syncthreads();

        int ahb0 = ((2 * mw) * 36 + s * 12) * 32 + lane;
        int ahb1 = ahb0 + 36 * 32;
        #pragma unroll 1
        for (int k12 = 0; k12 < 12; k12++) {
            uint4 ah0 = wf[ahb0 + k12 * 32];
            uint4 ah1 = wf[ahb1 + k12 * 32];
            unsigned bh0[4], bh1[4];
            ldsm4(bh0[0], bh0[1], bh0[2], bh0[3], vb0 + VT_HI_OFF + (unsigned)(k12 * 32));
            ldsm4(bh1[0], bh1[1], bh1[2], bh1[3], vb1 + VT_HI_OFF + (unsigned)(k12 * 32));
            mma_f16(acc[0][0], ah0, bh0[0], bh0[1]);
            mma_f16(acc[0][1], ah0, bh0[2], bh0[3]);
            mma_f16(acc[0][2], ah0, bh1[0], bh1[1]);
            mma_f16(acc[0][3], ah0, bh1[2], bh1[3]);
            mma_f16(acc[1][0], ah1, bh0[0], bh0[1]);
            mma_f16(acc[1][1], ah1, bh0[2], bh0[3]);
            mma_f16(acc[1][2], ah1, bh1[0], bh1[1]);
            mma_f16(acc[1][3], ah1, bh1[2], bh1[3]);
        }
        __syncthreads();
    }

    // epilogue: bn+relu+pool partial
    #pragma unroll
    for (int i = 0; i < 2; i++) {
        int coa = (2 * mw + i) * 16 + g;
        int cob = coa + 8;
        float sca = s_scale[coa], bia = s_bias[coa];
        float scb = s_scale[cob], bib = s_bias[cob];
        float sa = 0.f, sb = 0.f;
        #pragma unroll
        for (int nt = 0; nt < 4; nt++) {
            sa += fmaxf(acc[i][nt][0] * sca + bia, 0.f) + fmaxf(acc[i][nt][1] * sca + bia, 0.f);
            sb += fmaxf(acc[i][nt][2] * scb + bib, 0.f) + fmaxf(acc[i][nt][3] * scb + bib, 0.f);
        }
        sa += __shfl_xor_sync(0xffffffffu, sa, 1);
        sa += __shfl_xor_sync(0xffffffffu, sa, 2);
        sb += __shfl_xor_sync(0xffffffffu, sb, 1);
        sb += __shfl_xor_sync(0xffffffffu, sb, 2);
        if (t4 == 0) {
            g_partial[(size_t)(blk * 2 + nw) * 128 + coa] = sa;
            g_partial[(size_t)(blk * 2 + nw) * 128 + cob] = sb;
        }
    }
}

// ---------------- K4a: stage-1 partial reduction -----------------------------
__global__ void __launch_bounds__(128)
k4a_reduce()
{
    int b = blockIdx.x >> 3, seg = blockIdx.x & 7;
    int co = threadIdx.x;
    const float* pb = g_partial + ((size_t)b * 128 + seg * 16) * 128 + co;
    float s0 = 0.f, s1 = 0.f, s2 = 0.f, s3 = 0.f;
    #pragma unroll
    for (int i = 0; i < 4; i++) {
        s0 += pb[(i * 4 + 0) * 128];
        s1 += pb[(i * 4 + 1) * 128];
        s2 += pb[(i * 4 + 2) * 128];
        s3 += pb[(i * 4 + 3) * 128];
    }
    g_pool_seg[(b * 8 + seg) * 128 + co] = (s0 + s1) + (s2 + s3);
}

// ---------------- K4b: final reduce + fc1 + relu + fc2 -----------------------
__global__ void __launch_bounds__(256)
k4b_fc(const float* __restrict__ fc1w, const float* __restrict__ fc1b,
       const float* __restrict__ fc2w, const float* __restrict__ fc2b,
       float* __restrict__ out)
{
    __shared__ float sp[128];
    __shared__ float hid[256];
    int b = blockIdx.x, tid = threadIdx.x;
    if (tid < 128) {
        const float* ps = g_pool_seg + (size_t)b * 8 * 128 + tid;
        float s = 0.f;
        #pragma unroll
        for (int i = 0; i < 8; i++) s += ps[i * 128];
        sp[tid] = s * (1.f / 4096.f);
    }
    __syncthreads();
    {
        float a = fc1b[tid];
        #pragma unroll 8
        for (int j = 0; j < 128; j++) a += fc1w[tid * 128 + j] * sp[j];
        hid[tid] = fmaxf(a, 0.f);
    }
    __syncthreads();
    if (tid < 200) {
        float a = fc2b[tid];
        #pragma unroll 8
        for (int j = 0; j < 256; j++) a += fc2w[tid * 256 + j] * hid[j];
        out[b * 200 + tid] = a;
    }
}

// ---------------- launch -----------------------------------------------------
extern "C" void kernel_launch(void* const* d_in, const int* in_sizes, int n_in,
                              void* d_out, int out_size)
{
    const float* x    = (const float*)d_in[0];
    const float* o1w  = (const float*)d_in[1];
    const float* o1b  = (const float*)d_in[2];
    const float* c1w  = (const float*)d_in[3];
    const float* c1b  = (const float*)d_in[4];
    const float* g1   = (const float*)d_in[5];
    const float* be1  = (const float*)d_in[6];
    const float* m1   = (const float*)d_in[7];
    const float* v1   = (const float*)d_in[8];
    const float* o2w  = (const float*)d_in[9];
    const float* o2b  = (const float*)d_in[10];
    const float* c2w  = (const float*)d_in[11];
    const float* c2b  = (const float*)d_in[12];
    const float* g2   = (const float*)d_in[13];
    const float* be2  = (const float*)d_in[14];
    const float* m2   = (const float*)d_in[15];
    const float* v2   = (const float*)d_in[16];
    const float* f1w  = (const float*)d_in[17];
    const float* f1b  = (const float*)d_in[18];
    const float* f2w  = (const float*)d_in[19];
    const float* f2b  = (const float*)d_in[20];
    float* out = (float*)d_out;

    cudaFuncSetAttribute(k3_fused, cudaFuncAttributeMaxDynamicSharedMemorySize, K3_SMEM);

    k0_prep<<<184, 256>>>(c2w, o2w, c1w);
    k1_mma<<<2048, 256>>>(x, o1w, o1b, c1b, g1, be1, m1, v1);
    k3_fused<<<2048, 256, K3_SMEM>>>(o2b, c2b, g2, be2, m2, v2);
    k4a_reduce<<<256, 128>>>();
    k4b_fc<<<32, 256>>>(f1w, f1b, f2w, f2b, out);
}